// round 5
// baseline (speedup 1.0000x reference)
#include <cuda_runtime.h>
#include <cuda_bf16.h>
#include <math.h>
#include <cstdint>

// Problem constants (fixed by the reference)
#define BATCH 4
#define SEQ   2048
#define DMODEL 1024
#define NHEAD 16
#define HDIM  64
#define MTOT  (BATCH*SEQ)

typedef __nv_bfloat16 bf16;

// ---------------------------------------------------------------------------
// Scratch (device globals)
// ---------------------------------------------------------------------------
__device__ float g_q[BATCH*NHEAD*SEQ*HDIM];   // [B,H,S,HD] f32
__device__ float g_k[BATCH*NHEAD*SEQ*HDIM];
__device__ float g_v[BATCH*NHEAD*SEQ*HDIM];
__device__ float g_ctx[MTOT*DMODEL];          // [B,S,D] f32

__device__ bf16 g_xhi[MTOT*DMODEL];
__device__ bf16 g_xlo[MTOT*DMODEL];
__device__ bf16 g_whi[4*DMODEL*DMODEL];       // packed Wq,Wk,Wv,Wo
__device__ bf16 g_wlo[4*DMODEL*DMODEL];
__device__ bf16 g_chi[MTOT*DMODEL];
__device__ bf16 g_clo[MTOT*DMODEL];

__device__ bf16 g_qhi[BATCH*NHEAD*SEQ*HDIM];  // post-rope splits
__device__ bf16 g_qlo[BATCH*NHEAD*SEQ*HDIM];
__device__ bf16 g_khi[BATCH*NHEAD*SEQ*HDIM];
__device__ bf16 g_klo[BATCH*NHEAD*SEQ*HDIM];
__device__ bf16 g_vhi[BATCH*NHEAD*SEQ*HDIM];
__device__ bf16 g_vlo[BATCH*NHEAD*SEQ*HDIM];

// ---------------------------------------------------------------------------
// Helpers
// ---------------------------------------------------------------------------
__device__ __forceinline__ uint32_t smem_u32(const void* p) {
    uint32_t a;
    asm("{ .reg .u64 t; cvta.to.shared.u64 t, %1; cvt.u32.u64 %0, t; }"
        : "=r"(a) : "l"(p));
    return a;
}
__device__ __forceinline__ void cp16(uint32_t dst, const void* src) {
    asm volatile("cp.async.cg.shared.global [%0], [%1], 16;" :: "r"(dst), "l"(src));
}
__device__ __forceinline__ void cp_commit() {
    asm volatile("cp.async.commit_group;" ::: "memory");
}
__device__ __forceinline__ void cp_wait1() {
    asm volatile("cp.async.wait_group 1;" ::: "memory");
}
__device__ __forceinline__ void ldsm4(uint32_t* r, uint32_t addr) {
    asm volatile("ldmatrix.sync.aligned.m8n8.x4.shared.b16 {%0,%1,%2,%3}, [%4];"
                 : "=r"(r[0]), "=r"(r[1]), "=r"(r[2]), "=r"(r[3]) : "r"(addr));
}
__device__ __forceinline__ void ldsm4t(uint32_t* r, uint32_t addr) {
    asm volatile("ldmatrix.sync.aligned.m8n8.x4.trans.shared.b16 {%0,%1,%2,%3}, [%4];"
                 : "=r"(r[0]), "=r"(r[1]), "=r"(r[2]), "=r"(r[3]) : "r"(addr));
}
__device__ __forceinline__ void mma_bf16(float* c, const uint32_t* a, const uint32_t* b) {
    asm volatile(
        "mma.sync.aligned.m16n8k16.row.col.f32.bf16.bf16.f32 "
        "{%0,%1,%2,%3}, {%4,%5,%6,%7}, {%8,%9}, {%0,%1,%2,%3};"
        : "+f"(c[0]), "+f"(c[1]), "+f"(c[2]), "+f"(c[3])
        : "r"(a[0]), "r"(a[1]), "r"(a[2]), "r"(a[3]), "r"(b[0]), "r"(b[1]));
}
__device__ __forceinline__ uint32_t pack_bf16(float lo, float hi) {
    uint32_t r;
    asm("cvt.rn.bf16x2.f32 %0, %1, %2;" : "=r"(r) : "f"(hi), "f"(lo));
    return r;
}

// ---------------------------------------------------------------------------
// fp32 -> bf16 hi/lo split
// ---------------------------------------------------------------------------
__global__ void split_kernel(const float* __restrict__ x,
                             bf16* __restrict__ hi, bf16* __restrict__ lo, int n4)
{
    int i = blockIdx.x * blockDim.x + threadIdx.x;
    if (i >= n4) return;
    float4 v = ((const float4*)x)[i];
    bf16 h0 = __float2bfloat16(v.x), h1 = __float2bfloat16(v.y);
    bf16 h2 = __float2bfloat16(v.z), h3 = __float2bfloat16(v.w);
    bf16 l0 = __float2bfloat16(v.x - __bfloat162float(h0));
    bf16 l1 = __float2bfloat16(v.y - __bfloat162float(h1));
    bf16 l2 = __float2bfloat16(v.z - __bfloat162float(h2));
    bf16 l3 = __float2bfloat16(v.w - __bfloat162float(h3));
    ((__nv_bfloat162*)hi)[2*i]   = __halves2bfloat162(h0, h1);
    ((__nv_bfloat162*)hi)[2*i+1] = __halves2bfloat162(h2, h3);
    ((__nv_bfloat162*)lo)[2*i]   = __halves2bfloat162(l0, l1);
    ((__nv_bfloat162*)lo)[2*i+1] = __halves2bfloat162(l2, l3);
}

// ---------------------------------------------------------------------------
// HMMA GEMM: C[m,n] = sum_k A[m,k]*W[n,k] + bias[n]  (bf16x3 split, f32 acc)
// Tiles: 128x128x32, 8 warps (2M x 4N), warp tile 64x32, double-buffered.
// MODE 0: row-major out. MODE 1: scatter to [B,H,S,HD], z selects q/k/v.
// ---------------------------------------------------------------------------
#define GSTRIDE 40                        // bf16 per smem row (32+8 pad)
#define GTILE_B (128*GSTRIDE*2)           // 10240 bytes per tile
#define GSTAGE_B (4*GTILE_B)              // Ahi,Alo,Bhi,Blo
#define GSMEM (2*GSTAGE_B)                // 81920

__device__ __forceinline__ void g_load_stage(
    uint32_t smb, int s, int kt, int m0, int n0,
    const bf16* Ah, const bf16* Al, const bf16* wh, const bf16* wl, int tid)
{
    uint32_t base = smb + s * GSTAGE_B;
    int kc = kt * 32;
#pragma unroll
    for (int i = 0; i < 8; ++i) {
        int t = tid + i * 256;
        int tile = t >> 9;
        int r = (t >> 2) & 127;
        int c = t & 3;                    // 4 x 16B = 64B = 32 bf16 row  (OK)
        const bf16* src;
        if      (tile == 0) src = Ah + (size_t)(m0 + r) * DMODEL + kc + c * 8;
        else if (tile == 1) src = Al + (size_t)(m0 + r) * DMODEL + kc + c * 8;
        else if (tile == 2) src = wh + (size_t)(n0 + r) * DMODEL + kc + c * 8;
        else                src = wl + (size_t)(n0 + r) * DMODEL + kc + c * 8;
        cp16(base + tile * GTILE_B + r * (GSTRIDE*2) + c * 16, src);
    }
    cp_commit();
}

template<int MODE>
__global__ void __launch_bounds__(256, 1)
gemm_hmma(const bf16* __restrict__ Ah, const bf16* __restrict__ Al,
          const bf16* __restrict__ Wh, const bf16* __restrict__ Wl,
          const float* __restrict__ b0, const float* __restrict__ b1,
          const float* __restrict__ b2,
          float* __restrict__ dq, float* __restrict__ dk, float* __restrict__ dv)
{
    extern __shared__ char smc[];
    const uint32_t smb = smem_u32(smc);
    const int tid  = threadIdx.x;
    const int warp = tid >> 5, lane = tid & 31;
    const int z  = blockIdx.z;
    const int m0 = blockIdx.y * 128;
    const int n0 = blockIdx.x * 128;
    const int wm = (warp & 1) * 64;
    const int wn = (warp >> 1) * 32;

    const bf16* wh = Wh + ((size_t)z << 20);
    const bf16* wl = Wl + ((size_t)z << 20);
    const float* bias = (z == 0) ? b0 : (z == 1) ? b1 : b2;
    float* dst        = (z == 0) ? dq : (z == 1) ? dk : dv;

    float acc[4][4][4];
#pragma unroll
    for (int i = 0; i < 4; ++i)
#pragma unroll
        for (int j = 0; j < 4; ++j)
#pragma unroll
            for (int c = 0; c < 4; ++c) acc[i][j][c] = 0.f;

    g_load_stage(smb, 0, 0, m0, n0, Ah, Al, wh, wl, tid);
    g_load_stage(smb, 1, 1, m0, n0, Ah, Al, wh, wl, tid);

    const int arow = lane & 15, akh = lane >> 4;
    const int brow = lane & 7, bkh = (lane >> 3) & 1, bpr = lane >> 4;

    for (int kt = 0; kt < 32; ++kt) {
        uint32_t base = smb + (kt & 1) * GSTAGE_B;
        cp_wait1();
        __syncthreads();

#pragma unroll
        for (int kk = 0; kk < 2; ++kk) {
            uint32_t ah[4][4], al[4][4];
#pragma unroll
            for (int mt = 0; mt < 4; ++mt) {
                uint32_t ad = base + (wm + mt*16 + arow) * (GSTRIDE*2)
                                   + (kk*16 + akh*8) * 2;
                ldsm4(ah[mt], ad);
                ldsm4(al[mt], ad + GTILE_B);
            }
            uint32_t bh[4][2], bl[4][2];
#pragma unroll
            for (int p = 0; p < 2; ++p) {
                uint32_t bd = base + 2*GTILE_B
                            + (wn + p*16 + bpr*8 + brow) * (GSTRIDE*2)
                            + (kk*16 + bkh*8) * 2;
                uint32_t r[4];
                ldsm4(r, bd);
                bh[2*p][0]=r[0]; bh[2*p][1]=r[1]; bh[2*p+1][0]=r[2]; bh[2*p+1][1]=r[3];
                ldsm4(r, bd + GTILE_B);
                bl[2*p][0]=r[0]; bl[2*p][1]=r[1]; bl[2*p+1][0]=r[2]; bl[2*p+1][1]=r[3];
            }
#pragma unroll
            for (int mt = 0; mt < 4; ++mt)
#pragma unroll
                for (int nt = 0; nt < 4; ++nt) {
                    mma_bf16(acc[mt][nt], ah[mt], bh[nt]);
                    mma_bf16(acc[mt][nt], ah[mt], bl[nt]);
                    mma_bf16(acc[mt][nt], al[mt], bh[nt]);
                }
        }
        __syncthreads();
        if (kt + 2 < 32) g_load_stage(smb, kt & 1, kt + 2, m0, n0, Ah, Al, wh, wl, tid);
        else             cp_commit();
    }

    // epilogue
    const int gid = lane >> 2, tig = lane & 3;
#pragma unroll
    for (int mt = 0; mt < 4; ++mt) {
#pragma unroll
        for (int nt = 0; nt < 4; ++nt) {
#pragma unroll
            for (int half = 0; half < 2; ++half) {
                int mrow = m0 + wm + mt*16 + gid + half*8;
                int ncol = n0 + wn + nt*8 + tig*2;
                float2 v;
                v.x = acc[mt][nt][half*2]   + bias[ncol];
                v.y = acc[mt][nt][half*2+1] + bias[ncol+1];
                if (MODE == 0) {
                    *(float2*)&dst[(size_t)mrow * DMODEL + ncol] = v;
                } else {
                    int h  = ncol >> 6, hd = ncol & 63;
                    int bb = mrow >> 11, s = mrow & (SEQ-1);
                    *(float2*)&dst[(((size_t)(bb*NHEAD + h))*SEQ + s)*HDIM + hd] = v;
                }
            }
        }
    }
}

// ---------------------------------------------------------------------------
// RoPE + split to bf16 hi/lo (reference: "c"=sin half, "s"=cos half)
// ---------------------------------------------------------------------------
__global__ void rope_split(const float* __restrict__ q, const float* __restrict__ k,
                           bf16* __restrict__ qhi, bf16* __restrict__ qlo,
                           bf16* __restrict__ khi, bf16* __restrict__ klo)
{
    int idx = blockIdx.x*blockDim.x + threadIdx.x;
    if (idx >= BATCH*NHEAD*SEQ*(HDIM/2)) return;
    int j  = idx & 31;
    int s  = (idx >> 5) & (SEQ-1);
    int bh = idx >> 16;

    float inv = powf(10000.f, -(float)j / 32.f);
    float ang = (float)s * inv;
    float sn, cs;
    sincosf(ang, &sn, &cs);

    size_t base = ((size_t)bh*SEQ + s)*HDIM;
    {
        float x1 = q[base+j], x2 = q[base+j+32];
        float y1 = x1*sn - x2*cs, y2 = x2*sn + x1*cs;
        bf16 h1 = __float2bfloat16(y1), h2 = __float2bfloat16(y2);
        qhi[base+j] = h1; qhi[base+j+32] = h2;
        qlo[base+j]    = __float2bfloat16(y1 - __bfloat162float(h1));
        qlo[base+j+32] = __float2bfloat16(y2 - __bfloat162float(h2));
    }
    {
        float x1 = k[base+j], x2 = k[base+j+32];
        float y1 = x1*sn - x2*cs, y2 = x2*sn + x1*cs;
        bf16 h1 = __float2bfloat16(y1), h2 = __float2bfloat16(y2);
        khi[base+j] = h1; khi[base+j+32] = h2;
        klo[base+j]    = __float2bfloat16(y1 - __bfloat162float(h1));
        klo[base+j+32] = __float2bfloat16(y2 - __bfloat162float(h2));
    }
}

// ---------------------------------------------------------------------------
// Flash attention on HMMA, bf16x3. 64-row Q tiles, 4 warps (16 rows each),
// double-buffered K/V (hi/lo) tiles of 64x64.
// ---------------------------------------------------------------------------
#define ASTRIDE 72                    // bf16 per smem row (64+8 pad)
#define ATILE_B (64*ASTRIDE*2)        // 9216 bytes
#define ASMEM (2*ATILE_B + 8*ATILE_B) // Qhi,Qlo + 2 stages x (Khi,Klo,Vhi,Vlo)

__device__ __forceinline__ void a_load_kv(
    uint32_t smb, int s, int k0, const bf16* kh, const bf16* kl,
    const bf16* vh, const bf16* vl, int tid)
{
    uint32_t base = smb + 2*ATILE_B + s * 4*ATILE_B;
    // 4 tiles x 64 rows x 8 chunks (128B/row) = 2048 transfers
#pragma unroll
    for (int i = 0; i < 16; ++i) {
        int t = tid + i * 128;
        int tile = t >> 9;
        int r = (t >> 3) & 63;
        int c = t & 7;
        const bf16* src;
        if      (tile == 0) src = kh + (size_t)(k0 + r) * HDIM + c * 8;
        else if (tile == 1) src = kl + (size_t)(k0 + r) * HDIM + c * 8;
        else if (tile == 2) src = vh + (size_t)(k0 + r) * HDIM + c * 8;
        else                src = vl + (size_t)(k0 + r) * HDIM + c * 8;
        cp16(base + tile * ATILE_B + r * (ASTRIDE*2) + c * 16, src);
    }
    cp_commit();
}

__global__ void __launch_bounds__(128)
attn_hmma(const bf16* __restrict__ Qh, const bf16* __restrict__ Ql,
          const bf16* __restrict__ Kh, const bf16* __restrict__ Kl,
          const bf16* __restrict__ Vh, const bf16* __restrict__ Vl,
          float* __restrict__ ctx)
{
    extern __shared__ char smc[];
    const uint32_t smb = smem_u32(smc);
    const int tid = threadIdx.x;
    const int warp = tid >> 5, lane = tid & 31;
    const int q0 = blockIdx.x * 64;
    const int bh = blockIdx.y;

    const bf16* qhg = Qh + ((size_t)bh*SEQ + q0)*HDIM;
    const bf16* qlg = Ql + ((size_t)bh*SEQ + q0)*HDIM;
    const bf16* khg = Kh + (size_t)bh*SEQ*HDIM;
    const bf16* klg = Kl + (size_t)bh*SEQ*HDIM;
    const bf16* vhg = Vh + (size_t)bh*SEQ*HDIM;
    const bf16* vlg = Vl + (size_t)bh*SEQ*HDIM;

    // Q tiles (2 tiles x 64 rows x 8 chunks = 1024 transfers) + first KV stage
#pragma unroll
    for (int i = 0; i < 8; ++i) {
        int t = tid + i * 128;
        int tile = t >> 9;            // 0: hi, 1: lo
        int r = (t >> 3) & 63;
        int c = t & 7;
        const bf16* src = (tile ? qlg : qhg) + (size_t)r * HDIM + c * 8;
        cp16(smb + tile * ATILE_B + r * (ASTRIDE*2) + c * 16, src);
    }
    a_load_kv(smb, 0, 0, khg, klg, vhg, vlg, tid);   // commits group (Q + stage0)
    a_load_kv(smb, 1, 64, khg, klg, vhg, vlg, tid);

    const int gid = lane >> 2, tig = lane & 3;
    const int arow = lane & 15, akh = lane >> 4;
    const int brow = lane & 7, bkh = (lane >> 3) & 1, bpr = lane >> 4;

    uint32_t qh[4][4], ql[4][4];
    float o[8][4];
#pragma unroll
    for (int nt = 0; nt < 8; ++nt)
#pragma unroll
        for (int c = 0; c < 4; ++c) o[nt][c] = 0.f;
    float mrow0 = -INFINITY, mrow1 = -INFINITY, lrow0 = 0.f, lrow1 = 0.f;

    for (int kt = 0; kt < SEQ/64; ++kt) {
        uint32_t base = smb + 2*ATILE_B + (kt & 1) * 4*ATILE_B;
        cp_wait1();
        __syncthreads();

        if (kt == 0) {
            // load Q fragments once
#pragma unroll
            for (int kx = 0; kx < 4; ++kx) {
                uint32_t ad = smb + (warp*16 + arow) * (ASTRIDE*2) + (kx*16 + akh*8) * 2;
                ldsm4(qh[kx], ad);
                ldsm4(ql[kx], ad + ATILE_B);
            }
        }

        // S = Q K^T  (bf16x3)
        float s[8][4];
#pragma unroll
        for (int nt = 0; nt < 8; ++nt)
#pragma unroll
            for (int c = 0; c < 4; ++c) s[nt][c] = 0.f;

#pragma unroll
        for (int kx = 0; kx < 4; ++kx) {
            uint32_t kbh[8][2], kbl[8][2];
#pragma unroll
            for (int p = 0; p < 4; ++p) {
                uint32_t bd = base + (p*16 + bpr*8 + brow) * (ASTRIDE*2)
                            + (kx*16 + bkh*8) * 2;
                uint32_t r[4];
                ldsm4(r, bd);
                kbh[2*p][0]=r[0]; kbh[2*p][1]=r[1]; kbh[2*p+1][0]=r[2]; kbh[2*p+1][1]=r[3];
                ldsm4(r, bd + ATILE_B);
                kbl[2*p][0]=r[0]; kbl[2*p][1]=r[1]; kbl[2*p+1][0]=r[2]; kbl[2*p+1][1]=r[3];
            }
#pragma unroll
            for (int nt = 0; nt < 8; ++nt) {
                mma_bf16(s[nt], qh[kx], kbh[nt]);
                mma_bf16(s[nt], qh[kx], kbl[nt]);
                mma_bf16(s[nt], ql[kx], kbh[nt]);
            }
        }

        // online softmax (scale 1/8); rows gid (c0,c1) and gid+8 (c2,c3)
        float mx0 = -INFINITY, mx1 = -INFINITY;
#pragma unroll
        for (int nt = 0; nt < 8; ++nt) {
#pragma unroll
            for (int c = 0; c < 4; ++c) s[nt][c] *= 0.125f;
            mx0 = fmaxf(mx0, fmaxf(s[nt][0], s[nt][1]));
            mx1 = fmaxf(mx1, fmaxf(s[nt][2], s[nt][3]));
        }
        mx0 = fmaxf(mx0, __shfl_xor_sync(0xffffffffu, mx0, 1));
        mx0 = fmaxf(mx0, __shfl_xor_sync(0xffffffffu, mx0, 2));
        mx1 = fmaxf(mx1, __shfl_xor_sync(0xffffffffu, mx1, 1));
        mx1 = fmaxf(mx1, __shfl_xor_sync(0xffffffffu, mx1, 2));
        float mn0 = fmaxf(mrow0, mx0), mn1 = fmaxf(mrow1, mx1);
        float al0 = __expf(mrow0 - mn0), al1 = __expf(mrow1 - mn1);
        mrow0 = mn0; mrow1 = mn1;

        float ls0 = 0.f, ls1 = 0.f;
#pragma unroll
        for (int nt = 0; nt < 8; ++nt) {
            s[nt][0] = __expf(s[nt][0] - mn0);
            s[nt][1] = __expf(s[nt][1] - mn0);
            s[nt][2] = __expf(s[nt][2] - mn1);
            s[nt][3] = __expf(s[nt][3] - mn1);
            ls0 += s[nt][0] + s[nt][1];
            ls1 += s[nt][2] + s[nt][3];
        }
        ls0 += __shfl_xor_sync(0xffffffffu, ls0, 1);
        ls0 += __shfl_xor_sync(0xffffffffu, ls0, 2);
        ls1 += __shfl_xor_sync(0xffffffffu, ls1, 1);
        ls1 += __shfl_xor_sync(0xffffffffu, ls1, 2);
        lrow0 = lrow0 * al0 + ls0;
        lrow1 = lrow1 * al1 + ls1;

#pragma unroll
        for (int nt = 0; nt < 8; ++nt) {
            o[nt][0] *= al0; o[nt][1] *= al0;
            o[nt][2] *= al1; o[nt][3] *= al1;
        }

        // pack P into A-fragments (hi + residual lo)
        uint32_t ahi[4][4], alo[4][4];
#pragma unroll
        for (int j = 0; j < 4; ++j) {
#pragma unroll
            for (int rr = 0; rr < 4; ++rr) {
                int nt = 2*j + (rr >> 1);
                float p0 = s[nt][(rr & 1)*2], p1 = s[nt][(rr & 1)*2 + 1];
                uint32_t hpack = pack_bf16(p0, p1);
                ahi[j][rr] = hpack;
                __nv_bfloat162 hp = *(__nv_bfloat162*)&hpack;
                alo[j][rr] = pack_bf16(p0 - __bfloat162float(hp.x),
                                       p1 - __bfloat162float(hp.y));
            }
        }

        // O += P V
#pragma unroll
        for (int j = 0; j < 4; ++j) {
            uint32_t vbh[8][2], vbl[8][2];
#pragma unroll
            for (int p = 0; p < 4; ++p) {
                uint32_t vd = base + 2*ATILE_B
                            + (j*16 + (lane & 15)) * (ASTRIDE*2)
                            + (p*16 + (lane >> 4)*8) * 2;
                uint32_t r[4];
                ldsm4t(r, vd);
                vbh[2*p][0]=r[0]; vbh[2*p][1]=r[1]; vbh[2*p+1][0]=r[2]; vbh[2*p+1][1]=r[3];
                ldsm4t(r, vd + ATILE_B);
                vbl[2*p][0]=r[0]; vbl[2*p][1]=r[1]; vbl[2*p+1][0]=r[2]; vbl[2*p+1][1]=r[3];
            }
#pragma unroll
            for (int nt = 0; nt < 8; ++nt) {
                mma_bf16(o[nt], ahi[j], vbh[nt]);
                mma_bf16(o[nt], ahi[j], vbl[nt]);
                mma_bf16(o[nt], alo[j], vbh[nt]);
            }
        }

        __syncthreads();
        if (kt + 2 < SEQ/64) a_load_kv(smb, kt & 1, (kt+2)*64, khg, klg, vhg, vlg, tid);
        else                 cp_commit();
    }

    // write ctx
    const int b = bh >> 4, h = bh & 15;
    float il0 = 1.f / lrow0, il1 = 1.f / lrow1;
    int r0g = q0 + warp*16 + gid;
#pragma unroll
    for (int nt = 0; nt < 8; ++nt) {
        int col = h*HDIM + nt*8 + tig*2;
        float2 v0; v0.x = o[nt][0]*il0; v0.y = o[nt][1]*il0;
        float2 v1; v1.x = o[nt][2]*il1; v1.y = o[nt][3]*il1;
        *(float2*)&ctx[((size_t)(b*SEQ + r0g))*DMODEL + col] = v0;
        *(float2*)&ctx[((size_t)(b*SEQ + r0g + 8))*DMODEL + col] = v1;
    }
}

// ---------------------------------------------------------------------------
// Launch
// ---------------------------------------------------------------------------
extern "C" void kernel_launch(void* const* d_in, const int* in_sizes, int n_in,
                              void* d_out, int out_size)
{
    const float* X  = (const float*)d_in[0];
    const float* Wq = (const float*)d_in[1];
    const float* bq = (const float*)d_in[2];
    const float* Wk = (const float*)d_in[3];
    const float* bk = (const float*)d_in[4];
    const float* Wv = (const float*)d_in[5];
    const float* bv = (const float*)d_in[6];
    const float* Wo = (const float*)d_in[7];
    const float* bo = (const float*)d_in[8];
    float* out = (float*)d_out;

    float *pq, *pk, *pv, *pctx;
    bf16 *xhi, *xlo, *whi, *wlo, *chi, *clo;
    bf16 *qhi, *qlo, *khi, *klo, *vhi, *vlo;
    cudaGetSymbolAddress((void**)&pq,   g_q);
    cudaGetSymbolAddress((void**)&pk,   g_k);
    cudaGetSymbolAddress((void**)&pv,   g_v);
    cudaGetSymbolAddress((void**)&pctx, g_ctx);
    cudaGetSymbolAddress((void**)&xhi,  g_xhi);
    cudaGetSymbolAddress((void**)&xlo,  g_xlo);
    cudaGetSymbolAddress((void**)&whi,  g_whi);
    cudaGetSymbolAddress((void**)&wlo,  g_wlo);
    cudaGetSymbolAddress((void**)&chi,  g_chi);
    cudaGetSymbolAddress((void**)&clo,  g_clo);
    cudaGetSymbolAddress((void**)&qhi,  g_qhi);
    cudaGetSymbolAddress((void**)&qlo,  g_qlo);
    cudaGetSymbolAddress((void**)&khi,  g_khi);
    cudaGetSymbolAddress((void**)&klo,  g_klo);
    cudaGetSymbolAddress((void**)&vhi,  g_vhi);
    cudaGetSymbolAddress((void**)&vlo,  g_vlo);

    cudaFuncSetAttribute(gemm_hmma<0>, cudaFuncAttributeMaxDynamicSharedMemorySize, GSMEM);
    cudaFuncSetAttribute(gemm_hmma<1>, cudaFuncAttributeMaxDynamicSharedMemorySize, GSMEM);
    cudaFuncSetAttribute(attn_hmma, cudaFuncAttributeMaxDynamicSharedMemorySize, ASMEM);

    // splits
    split_kernel<<<(MTOT*DMODEL/4)/256, 256>>>(X, xhi, xlo, MTOT*DMODEL/4);
    split_kernel<<<(DMODEL*DMODEL/4)/256, 256>>>(Wq, whi + 0*1048576, wlo + 0*1048576, DMODEL*DMODEL/4);
    split_kernel<<<(DMODEL*DMODEL/4)/256, 256>>>(Wk, whi + 1*1048576, wlo + 1*1048576, DMODEL*DMODEL/4);
    split_kernel<<<(DMODEL*DMODEL/4)/256, 256>>>(Wv, whi + 2*1048576, wlo + 2*1048576, DMODEL*DMODEL/4);
    split_kernel<<<(DMODEL*DMODEL/4)/256, 256>>>(Wo, whi + 3*1048576, wlo + 3*1048576, DMODEL*DMODEL/4);

    // fused QKV projection (z = 0/1/2)
    gemm_hmma<1><<<dim3(DMODEL/128, MTOT/128, 3), 256, GSMEM>>>(
        xhi, xlo, whi, wlo, bq, bk, bv, pq, pk, pv);

    // rope + split q/k, split v
    rope_split<<<(BATCH*NHEAD*SEQ*(HDIM/2))/256, 256>>>(pq, pk, qhi, qlo, khi, klo);
    split_kernel<<<(BATCH*NHEAD*SEQ*HDIM/4)/256, 256>>>(pv, vhi, vlo, BATCH*NHEAD*SEQ*HDIM/4);

    // attention
    attn_hmma<<<dim3(SEQ/64, BATCH*NHEAD), 128, ASMEM>>>(
        qhi, qlo, khi, klo, vhi, vlo, pctx);

    // output projection
    split_kernel<<<(MTOT*DMODEL/4)/256, 256>>>(pctx, chi, clo, MTOT*DMODEL/4);
    gemm_hmma<0><<<dim3(DMODEL/128, MTOT/128, 1), 256, GSMEM>>>(
        chi, clo, whi + 3*1048576, wlo + 3*1048576, bo, bo, bo, out, out, out);
}

// round 6
// speedup vs baseline: 1.0087x; 1.0087x over previous
#include <cuda_runtime.h>
#include <cuda_bf16.h>
#include <math.h>
#include <cstdint>

// Problem constants (fixed by the reference)
#define BATCH 4
#define SEQ   2048
#define DMODEL 1024
#define NHEAD 16
#define HDIM  64
#define MTOT  (BATCH*SEQ)

typedef __nv_bfloat16 bf16;

// ---------------------------------------------------------------------------
// Scratch (device globals)
// ---------------------------------------------------------------------------
__device__ float g_q[BATCH*NHEAD*SEQ*HDIM];   // [B,H,S,HD] f32
__device__ float g_k[BATCH*NHEAD*SEQ*HDIM];
__device__ float g_v[BATCH*NHEAD*SEQ*HDIM];
__device__ float g_ctx[MTOT*DMODEL];          // [B,S,D] f32

__device__ bf16 g_xhi[MTOT*DMODEL];
__device__ bf16 g_xlo[MTOT*DMODEL];
__device__ bf16 g_whi[4*DMODEL*DMODEL];       // packed Wq,Wk,Wv,Wo
__device__ bf16 g_wlo[4*DMODEL*DMODEL];
__device__ bf16 g_chi[MTOT*DMODEL];
__device__ bf16 g_clo[MTOT*DMODEL];

__device__ bf16 g_qhi[BATCH*NHEAD*SEQ*HDIM];  // post-rope splits
__device__ bf16 g_qlo[BATCH*NHEAD*SEQ*HDIM];
__device__ bf16 g_khi[BATCH*NHEAD*SEQ*HDIM];
__device__ bf16 g_klo[BATCH*NHEAD*SEQ*HDIM];
__device__ bf16 g_vhi[BATCH*NHEAD*SEQ*HDIM];
__device__ bf16 g_vlo[BATCH*NHEAD*SEQ*HDIM];

// ---------------------------------------------------------------------------
// Helpers
// ---------------------------------------------------------------------------
__device__ __forceinline__ uint32_t smem_u32(const void* p) {
    uint32_t a;
    asm("{ .reg .u64 t; cvta.to.shared.u64 t, %1; cvt.u32.u64 %0, t; }"
        : "=r"(a) : "l"(p));
    return a;
}
__device__ __forceinline__ void cp16(uint32_t dst, const void* src) {
    asm volatile("cp.async.cg.shared.global [%0], [%1], 16;" :: "r"(dst), "l"(src));
}
__device__ __forceinline__ void cp_commit() {
    asm volatile("cp.async.commit_group;" ::: "memory");
}
__device__ __forceinline__ void cp_wait2() {
    asm volatile("cp.async.wait_group 2;" ::: "memory");
}
__device__ __forceinline__ void ldsm4(uint32_t* r, uint32_t addr) {
    asm volatile("ldmatrix.sync.aligned.m8n8.x4.shared.b16 {%0,%1,%2,%3}, [%4];"
                 : "=r"(r[0]), "=r"(r[1]), "=r"(r[2]), "=r"(r[3]) : "r"(addr));
}
__device__ __forceinline__ void ldsm4t(uint32_t* r, uint32_t addr) {
    asm volatile("ldmatrix.sync.aligned.m8n8.x4.trans.shared.b16 {%0,%1,%2,%3}, [%4];"
                 : "=r"(r[0]), "=r"(r[1]), "=r"(r[2]), "=r"(r[3]) : "r"(addr));
}
__device__ __forceinline__ void mma_bf16(float* c, const uint32_t* a, const uint32_t* b) {
    asm volatile(
        "mma.sync.aligned.m16n8k16.row.col.f32.bf16.bf16.f32 "
        "{%0,%1,%2,%3}, {%4,%5,%6,%7}, {%8,%9}, {%0,%1,%2,%3};"
        : "+f"(c[0]), "+f"(c[1]), "+f"(c[2]), "+f"(c[3])
        : "r"(a[0]), "r"(a[1]), "r"(a[2]), "r"(a[3]), "r"(b[0]), "r"(b[1]));
}
__device__ __forceinline__ uint32_t pack_bf16(float lo, float hi) {
    uint32_t r;
    asm("cvt.rn.bf16x2.f32 %0, %1, %2;" : "=r"(r) : "f"(hi), "f"(lo));
    return r;
}

// ---------------------------------------------------------------------------
// fp32 -> bf16 hi/lo split
// ---------------------------------------------------------------------------
__global__ void split_kernel(const float* __restrict__ x,
                             bf16* __restrict__ hi, bf16* __restrict__ lo, int n4)
{
    int i = blockIdx.x * blockDim.x + threadIdx.x;
    if (i >= n4) return;
    float4 v = ((const float4*)x)[i];
    bf16 h0 = __float2bfloat16(v.x), h1 = __float2bfloat16(v.y);
    bf16 h2 = __float2bfloat16(v.z), h3 = __float2bfloat16(v.w);
    bf16 l0 = __float2bfloat16(v.x - __bfloat162float(h0));
    bf16 l1 = __float2bfloat16(v.y - __bfloat162float(h1));
    bf16 l2 = __float2bfloat16(v.z - __bfloat162float(h2));
    bf16 l3 = __float2bfloat16(v.w - __bfloat162float(h3));
    ((__nv_bfloat162*)hi)[2*i]   = __halves2bfloat162(h0, h1);
    ((__nv_bfloat162*)hi)[2*i+1] = __halves2bfloat162(h2, h3);
    ((__nv_bfloat162*)lo)[2*i]   = __halves2bfloat162(l0, l1);
    ((__nv_bfloat162*)lo)[2*i+1] = __halves2bfloat162(l2, l3);
}

// ---------------------------------------------------------------------------
// HMMA GEMM: C[m,n] = sum_k A[m,k]*W[n,k] + bias[n]  (bf16x3 split, f32 acc)
// Tiles: 128x128x32, 8 warps (2M x 4N), warp tile 64x32, 3-stage cp.async.
// MODE 0: row-major out. MODE 1: scatter to [B,H,S,HD], z selects q/k/v.
// ---------------------------------------------------------------------------
#define GSTRIDE 40                        // bf16 per smem row (32+8 pad)
#define GTILE_B (128*GSTRIDE*2)           // 10240 bytes per tile
#define GSTAGE_B (4*GTILE_B)              // Ahi,Alo,Bhi,Blo
#define GSTAGES 3
#define GSMEM (GSTAGES*GSTAGE_B)          // 122880

__device__ __forceinline__ void g_load_stage(
    uint32_t smb, int s, int kt, int m0, int n0,
    const bf16* Ah, const bf16* Al, const bf16* wh, const bf16* wl, int tid)
{
    uint32_t base = smb + s * GSTAGE_B;
    int kc = kt * 32;
#pragma unroll
    for (int i = 0; i < 8; ++i) {
        int t = tid + i * 256;
        int tile = t >> 9;
        int r = (t >> 2) & 127;
        int c = t & 3;
        const bf16* src;
        if      (tile == 0) src = Ah + (size_t)(m0 + r) * DMODEL + kc + c * 8;
        else if (tile == 1) src = Al + (size_t)(m0 + r) * DMODEL + kc + c * 8;
        else if (tile == 2) src = wh + (size_t)(n0 + r) * DMODEL + kc + c * 8;
        else                src = wl + (size_t)(n0 + r) * DMODEL + kc + c * 8;
        cp16(base + tile * GTILE_B + r * (GSTRIDE*2) + c * 16, src);
    }
    cp_commit();
}

template<int MODE>
__global__ void __launch_bounds__(256, 1)
gemm_hmma(const bf16* __restrict__ Ah, const bf16* __restrict__ Al,
          const bf16* __restrict__ Wh, const bf16* __restrict__ Wl,
          const float* __restrict__ b0, const float* __restrict__ b1,
          const float* __restrict__ b2,
          float* __restrict__ dq, float* __restrict__ dk, float* __restrict__ dv)
{
    extern __shared__ char smc[];
    const uint32_t smb = smem_u32(smc);
    const int tid  = threadIdx.x;
    const int warp = tid >> 5, lane = tid & 31;
    const int z  = blockIdx.z;
    const int m0 = blockIdx.y * 128;
    const int n0 = blockIdx.x * 128;
    const int wm = (warp & 1) * 64;
    const int wn = (warp >> 1) * 32;

    const bf16* wh = Wh + ((size_t)z << 20);
    const bf16* wl = Wl + ((size_t)z << 20);
    const float* bias = (z == 0) ? b0 : (z == 1) ? b1 : b2;
    float* dst        = (z == 0) ? dq : (z == 1) ? dk : dv;

    float acc[4][4][4];
#pragma unroll
    for (int i = 0; i < 4; ++i)
#pragma unroll
        for (int j = 0; j < 4; ++j)
#pragma unroll
            for (int c = 0; c < 4; ++c) acc[i][j][c] = 0.f;

    g_load_stage(smb, 0, 0, m0, n0, Ah, Al, wh, wl, tid);
    g_load_stage(smb, 1, 1, m0, n0, Ah, Al, wh, wl, tid);
    g_load_stage(smb, 2, 2, m0, n0, Ah, Al, wh, wl, tid);

    const int arow = lane & 15, akh = lane >> 4;
    const int brow = lane & 7, bkh = (lane >> 3) & 1, bpr = lane >> 4;

    int stage = 0;
    for (int kt = 0; kt < 32; ++kt) {
        uint32_t base = smb + stage * GSTAGE_B;
        cp_wait2();
        __syncthreads();

#pragma unroll
        for (int kk = 0; kk < 2; ++kk) {
            uint32_t ah[4][4], al[4][4];
#pragma unroll
            for (int mt = 0; mt < 4; ++mt) {
                uint32_t ad = base + (wm + mt*16 + arow) * (GSTRIDE*2)
                                   + (kk*16 + akh*8) * 2;
                ldsm4(ah[mt], ad);
                ldsm4(al[mt], ad + GTILE_B);
            }
            uint32_t bh[4][2], bl[4][2];
#pragma unroll
            for (int p = 0; p < 2; ++p) {
                uint32_t bd = base + 2*GTILE_B
                            + (wn + p*16 + bpr*8 + brow) * (GSTRIDE*2)
                            + (kk*16 + bkh*8) * 2;
                uint32_t r[4];
                ldsm4(r, bd);
                bh[2*p][0]=r[0]; bh[2*p][1]=r[1]; bh[2*p+1][0]=r[2]; bh[2*p+1][1]=r[3];
                ldsm4(r, bd + GTILE_B);
                bl[2*p][0]=r[0]; bl[2*p][1]=r[1]; bl[2*p+1][0]=r[2]; bl[2*p+1][1]=r[3];
            }
#pragma unroll
            for (int mt = 0; mt < 4; ++mt)
#pragma unroll
                for (int nt = 0; nt < 4; ++nt) {
                    mma_bf16(acc[mt][nt], ah[mt], bh[nt]);
                    mma_bf16(acc[mt][nt], ah[mt], bl[nt]);
                    mma_bf16(acc[mt][nt], al[mt], bh[nt]);
                }
        }
        __syncthreads();
        if (kt + 3 < 32) g_load_stage(smb, stage, kt + 3, m0, n0, Ah, Al, wh, wl, tid);
        else             cp_commit();
        stage = (stage + 1 == GSTAGES) ? 0 : stage + 1;
    }

    // epilogue
    const int gid = lane >> 2, tig = lane & 3;
#pragma unroll
    for (int mt = 0; mt < 4; ++mt) {
#pragma unroll
        for (int nt = 0; nt < 4; ++nt) {
#pragma unroll
            for (int half = 0; half < 2; ++half) {
                int mrow = m0 + wm + mt*16 + gid + half*8;
                int ncol = n0 + wn + nt*8 + tig*2;
                float2 v;
                v.x = acc[mt][nt][half*2]   + bias[ncol];
                v.y = acc[mt][nt][half*2+1] + bias[ncol+1];
                if (MODE == 0) {
                    *(float2*)&dst[(size_t)mrow * DMODEL + ncol] = v;
                } else {
                    int h  = ncol >> 6, hd = ncol & 63;
                    int bb = mrow >> 11, s = mrow & (SEQ-1);
                    *(float2*)&dst[(((size_t)(bb*NHEAD + h))*SEQ + s)*HDIM + hd] = v;
                }
            }
        }
    }
}

// ---------------------------------------------------------------------------
// RoPE + split to bf16 hi/lo (reference: "c"=sin half, "s"=cos half)
// ---------------------------------------------------------------------------
__global__ void rope_split(const float* __restrict__ q, const float* __restrict__ k,
                           bf16* __restrict__ qhi, bf16* __restrict__ qlo,
                           bf16* __restrict__ khi, bf16* __restrict__ klo)
{
    int idx = blockIdx.x*blockDim.x + threadIdx.x;
    if (idx >= BATCH*NHEAD*SEQ*(HDIM/2)) return;
    int j  = idx & 31;
    int s  = (idx >> 5) & (SEQ-1);
    int bh = idx >> 16;

    float inv = powf(10000.f, -(float)j / 32.f);
    float ang = (float)s * inv;
    float sn, cs;
    sincosf(ang, &sn, &cs);

    size_t base = ((size_t)bh*SEQ + s)*HDIM;
    {
        float x1 = q[base+j], x2 = q[base+j+32];
        float y1 = x1*sn - x2*cs, y2 = x2*sn + x1*cs;
        bf16 h1 = __float2bfloat16(y1), h2 = __float2bfloat16(y2);
        qhi[base+j] = h1; qhi[base+j+32] = h2;
        qlo[base+j]    = __float2bfloat16(y1 - __bfloat162float(h1));
        qlo[base+j+32] = __float2bfloat16(y2 - __bfloat162float(h2));
    }
    {
        float x1 = k[base+j], x2 = k[base+j+32];
        float y1 = x1*sn - x2*cs, y2 = x2*sn + x1*cs;
        bf16 h1 = __float2bfloat16(y1), h2 = __float2bfloat16(y2);
        khi[base+j] = h1; khi[base+j+32] = h2;
        klo[base+j]    = __float2bfloat16(y1 - __bfloat162float(h1));
        klo[base+j+32] = __float2bfloat16(y2 - __bfloat162float(h2));
    }
}

// ---------------------------------------------------------------------------
// Flash attention on HMMA, bf16x3. 128-row Q tiles, 8 warps (16 rows each),
// 3-stage cp.async ring of 64-row K/V (hi/lo) tiles.
// ---------------------------------------------------------------------------
#define ASTRIDE 72                        // bf16 per smem row (64+8 pad)
#define ATILE_B (64*ASTRIDE*2)            // 9216 bytes (64-row tile)
#define AQTILE_B (128*ASTRIDE*2)          // 18432 bytes (128-row Q tile)
#define AKV_STAGE (4*ATILE_B)             // Khi,Klo,Vhi,Vlo
#define ASTAGES 3
#define ASMEM (2*AQTILE_B + ASTAGES*AKV_STAGE)   // 36864 + 110592 = 147456

__device__ __forceinline__ void a_load_kv(
    uint32_t smb, int s, int k0, const bf16* kh, const bf16* kl,
    const bf16* vh, const bf16* vl, int tid)
{
    uint32_t base = smb + 2*AQTILE_B + s * AKV_STAGE;
    // 4 tiles x 64 rows x 8 chunks (128B/row) = 2048 transfers / 256 threads
#pragma unroll
    for (int i = 0; i < 8; ++i) {
        int t = tid + i * 256;
        int tile = t >> 9;
        int r = (t >> 3) & 63;
        int c = t & 7;
        const bf16* src;
        if      (tile == 0) src = kh + (size_t)(k0 + r) * HDIM + c * 8;
        else if (tile == 1) src = kl + (size_t)(k0 + r) * HDIM + c * 8;
        else if (tile == 2) src = vh + (size_t)(k0 + r) * HDIM + c * 8;
        else                src = vl + (size_t)(k0 + r) * HDIM + c * 8;
        cp16(base + tile * ATILE_B + r * (ASTRIDE*2) + c * 16, src);
    }
    cp_commit();
}

__global__ void __launch_bounds__(256, 1)
attn_hmma(const bf16* __restrict__ Qh, const bf16* __restrict__ Ql,
          const bf16* __restrict__ Kh, const bf16* __restrict__ Kl,
          const bf16* __restrict__ Vh, const bf16* __restrict__ Vl,
          float* __restrict__ ctx)
{
    extern __shared__ char smc[];
    const uint32_t smb = smem_u32(smc);
    const int tid = threadIdx.x;
    const int warp = tid >> 5, lane = tid & 31;
    const int q0 = blockIdx.x * 128;
    const int bh = blockIdx.y;

    const bf16* qhg = Qh + ((size_t)bh*SEQ + q0)*HDIM;
    const bf16* qlg = Ql + ((size_t)bh*SEQ + q0)*HDIM;
    const bf16* khg = Kh + (size_t)bh*SEQ*HDIM;
    const bf16* klg = Kl + (size_t)bh*SEQ*HDIM;
    const bf16* vhg = Vh + (size_t)bh*SEQ*HDIM;
    const bf16* vlg = Vl + (size_t)bh*SEQ*HDIM;

    // Q tiles: 2 tiles x 128 rows x 8 chunks = 2048 transfers / 256 threads
#pragma unroll
    for (int i = 0; i < 8; ++i) {
        int t = tid + i * 256;
        int tile = t >> 10;           // 0: hi, 1: lo
        int r = (t >> 3) & 127;
        int c = t & 7;
        const bf16* src = (tile ? qlg : qhg) + (size_t)r * HDIM + c * 8;
        cp16(smb + tile * AQTILE_B + r * (ASTRIDE*2) + c * 16, src);
    }
    a_load_kv(smb, 0, 0,   khg, klg, vhg, vlg, tid);   // group 0 (incl. Q)
    a_load_kv(smb, 1, 64,  khg, klg, vhg, vlg, tid);   // group 1
    a_load_kv(smb, 2, 128, khg, klg, vhg, vlg, tid);   // group 2

    const int gid = lane >> 2, tig = lane & 3;
    const int arow = lane & 15, akh = lane >> 4;
    const int brow = lane & 7, bkh = (lane >> 3) & 1, bpr = lane >> 4;

    uint32_t qh[4][4], ql[4][4];
    float o[8][4];
#pragma unroll
    for (int nt = 0; nt < 8; ++nt)
#pragma unroll
        for (int c = 0; c < 4; ++c) o[nt][c] = 0.f;
    float mrow0 = -INFINITY, mrow1 = -INFINITY, lrow0 = 0.f, lrow1 = 0.f;

    int stage = 0;
    for (int kt = 0; kt < SEQ/64; ++kt) {
        uint32_t base = smb + 2*AQTILE_B + stage * AKV_STAGE;
        cp_wait2();
        __syncthreads();

        if (kt == 0) {
            // load Q fragments once (warp w owns rows w*16 .. w*16+15)
#pragma unroll
            for (int kx = 0; kx < 4; ++kx) {
                uint32_t ad = smb + (warp*16 + arow) * (ASTRIDE*2) + (kx*16 + akh*8) * 2;
                ldsm4(qh[kx], ad);
                ldsm4(ql[kx], ad + AQTILE_B);
            }
        }

        // S = Q K^T  (bf16x3)
        float s[8][4];
#pragma unroll
        for (int nt = 0; nt < 8; ++nt)
#pragma unroll
            for (int c = 0; c < 4; ++c) s[nt][c] = 0.f;

#pragma unroll
        for (int kx = 0; kx < 4; ++kx) {
            uint32_t kbh[8][2], kbl[8][2];
#pragma unroll
            for (int p = 0; p < 4; ++p) {
                uint32_t bd = base + (p*16 + bpr*8 + brow) * (ASTRIDE*2)
                            + (kx*16 + bkh*8) * 2;
                uint32_t r[4];
                ldsm4(r, bd);
                kbh[2*p][0]=r[0]; kbh[2*p][1]=r[1]; kbh[2*p+1][0]=r[2]; kbh[2*p+1][1]=r[3];
                ldsm4(r, bd + ATILE_B);
                kbl[2*p][0]=r[0]; kbl[2*p][1]=r[1]; kbl[2*p+1][0]=r[2]; kbl[2*p+1][1]=r[3];
            }
#pragma unroll
            for (int nt = 0; nt < 8; ++nt) {
                mma_bf16(s[nt], qh[kx], kbh[nt]);
                mma_bf16(s[nt], qh[kx], kbl[nt]);
                mma_bf16(s[nt], ql[kx], kbh[nt]);
            }
        }

        // online softmax (scale 1/8); rows gid (c0,c1) and gid+8 (c2,c3)
        float mx0 = -INFINITY, mx1 = -INFINITY;
#pragma unroll
        for (int nt = 0; nt < 8; ++nt) {
#pragma unroll
            for (int c = 0; c < 4; ++c) s[nt][c] *= 0.125f;
            mx0 = fmaxf(mx0, fmaxf(s[nt][0], s[nt][1]));
            mx1 = fmaxf(mx1, fmaxf(s[nt][2], s[nt][3]));
        }
        mx0 = fmaxf(mx0, __shfl_xor_sync(0xffffffffu, mx0, 1));
        mx0 = fmaxf(mx0, __shfl_xor_sync(0xffffffffu, mx0, 2));
        mx1 = fmaxf(mx1, __shfl_xor_sync(0xffffffffu, mx1, 1));
        mx1 = fmaxf(mx1, __shfl_xor_sync(0xffffffffu, mx1, 2));
        float mn0 = fmaxf(mrow0, mx0), mn1 = fmaxf(mrow1, mx1);
        float al0 = __expf(mrow0 - mn0), al1 = __expf(mrow1 - mn1);
        mrow0 = mn0; mrow1 = mn1;

        float ls0 = 0.f, ls1 = 0.f;
#pragma unroll
        for (int nt = 0; nt < 8; ++nt) {
            s[nt][0] = __expf(s[nt][0] - mn0);
            s[nt][1] = __expf(s[nt][1] - mn0);
            s[nt][2] = __expf(s[nt][2] - mn1);
            s[nt][3] = __expf(s[nt][3] - mn1);
            ls0 += s[nt][0] + s[nt][1];
            ls1 += s[nt][2] + s[nt][3];
        }
        ls0 += __shfl_xor_sync(0xffffffffu, ls0, 1);
        ls0 += __shfl_xor_sync(0xffffffffu, ls0, 2);
        ls1 += __shfl_xor_sync(0xffffffffu, ls1, 1);
        ls1 += __shfl_xor_sync(0xffffffffu, ls1, 2);
        lrow0 = lrow0 * al0 + ls0;
        lrow1 = lrow1 * al1 + ls1;

#pragma unroll
        for (int nt = 0; nt < 8; ++nt) {
            o[nt][0] *= al0; o[nt][1] *= al0;
            o[nt][2] *= al1; o[nt][3] *= al1;
        }

        // pack P into A-fragments (hi + residual lo)
        uint32_t ahi[4][4], alo[4][4];
#pragma unroll
        for (int j = 0; j < 4; ++j) {
#pragma unroll
            for (int rr = 0; rr < 4; ++rr) {
                int nt = 2*j + (rr >> 1);
                float p0 = s[nt][(rr & 1)*2], p1 = s[nt][(rr & 1)*2 + 1];
                uint32_t hpack = pack_bf16(p0, p1);
                ahi[j][rr] = hpack;
                __nv_bfloat162 hp = *(__nv_bfloat162*)&hpack;
                alo[j][rr] = pack_bf16(p0 - __bfloat162float(hp.x),
                                       p1 - __bfloat162float(hp.y));
            }
        }

        // O += P V
#pragma unroll
        for (int j = 0; j < 4; ++j) {
            uint32_t vbh[8][2], vbl[8][2];
#pragma unroll
            for (int p = 0; p < 4; ++p) {
                uint32_t vd = base + 2*ATILE_B
                            + (j*16 + (lane & 15)) * (ASTRIDE*2)
                            + (p*16 + (lane >> 4)*8) * 2;
                uint32_t r[4];
                ldsm4t(r, vd);
                vbh[2*p][0]=r[0]; vbh[2*p][1]=r[1]; vbh[2*p+1][0]=r[2]; vbh[2*p+1][1]=r[3];
                ldsm4t(r, vd + ATILE_B);
                vbl[2*p][0]=r[0]; vbl[2*p][1]=r[1]; vbl[2*p+1][0]=r[2]; vbl[2*p+1][1]=r[3];
            }
#pragma unroll
            for (int nt = 0; nt < 8; ++nt) {
                mma_bf16(o[nt], ahi[j], vbh[nt]);
                mma_bf16(o[nt], ahi[j], vbl[nt]);
                mma_bf16(o[nt], alo[j], vbh[nt]);
            }
        }

        __syncthreads();
        if (kt + 3 < SEQ/64) a_load_kv(smb, stage, (kt+3)*64, khg, klg, vhg, vlg, tid);
        else                 cp_commit();
        stage = (stage + 1 == ASTAGES) ? 0 : stage + 1;
    }

    // write ctx
    const int b = bh >> 4, h = bh & 15;
    float il0 = 1.f / lrow0, il1 = 1.f / lrow1;
    int r0g = q0 + warp*16 + gid;
#pragma unroll
    for (int nt = 0; nt < 8; ++nt) {
        int col = h*HDIM + nt*8 + tig*2;
        float2 v0; v0.x = o[nt][0]*il0; v0.y = o[nt][1]*il0;
        float2 v1; v1.x = o[nt][2]*il1; v1.y = o[nt][3]*il1;
        *(float2*)&ctx[((size_t)(b*SEQ + r0g))*DMODEL + col] = v0;
        *(float2*)&ctx[((size_t)(b*SEQ + r0g + 8))*DMODEL + col] = v1;
    }
}

// ---------------------------------------------------------------------------
// Launch
// ---------------------------------------------------------------------------
extern "C" void kernel_launch(void* const* d_in, const int* in_sizes, int n_in,
                              void* d_out, int out_size)
{
    const float* X  = (const float*)d_in[0];
    const float* Wq = (const float*)d_in[1];
    const float* bq = (const float*)d_in[2];
    const float* Wk = (const float*)d_in[3];
    const float* bk = (const float*)d_in[4];
    const float* Wv = (const float*)d_in[5];
    const float* bv = (const float*)d_in[6];
    const float* Wo = (const float*)d_in[7];
    const float* bo = (const float*)d_in[8];
    float* out = (float*)d_out;

    float *pq, *pk, *pv, *pctx;
    bf16 *xhi, *xlo, *whi, *wlo, *chi, *clo;
    bf16 *qhi, *qlo, *khi, *klo, *vhi, *vlo;
    cudaGetSymbolAddress((void**)&pq,   g_q);
    cudaGetSymbolAddress((void**)&pk,   g_k);
    cudaGetSymbolAddress((void**)&pv,   g_v);
    cudaGetSymbolAddress((void**)&pctx, g_ctx);
    cudaGetSymbolAddress((void**)&xhi,  g_xhi);
    cudaGetSymbolAddress((void**)&xlo,  g_xlo);
    cudaGetSymbolAddress((void**)&whi,  g_whi);
    cudaGetSymbolAddress((void**)&wlo,  g_wlo);
    cudaGetSymbolAddress((void**)&chi,  g_chi);
    cudaGetSymbolAddress((void**)&clo,  g_clo);
    cudaGetSymbolAddress((void**)&qhi,  g_qhi);
    cudaGetSymbolAddress((void**)&qlo,  g_qlo);
    cudaGetSymbolAddress((void**)&khi,  g_khi);
    cudaGetSymbolAddress((void**)&klo,  g_klo);
    cudaGetSymbolAddress((void**)&vhi,  g_vhi);
    cudaGetSymbolAddress((void**)&vlo,  g_vlo);

    cudaFuncSetAttribute(gemm_hmma<0>, cudaFuncAttributeMaxDynamicSharedMemorySize, GSMEM);
    cudaFuncSetAttribute(gemm_hmma<1>, cudaFuncAttributeMaxDynamicSharedMemorySize, GSMEM);
    cudaFuncSetAttribute(attn_hmma, cudaFuncAttributeMaxDynamicSharedMemorySize, ASMEM);

    // splits
    split_kernel<<<(MTOT*DMODEL/4)/256, 256>>>(X, xhi, xlo, MTOT*DMODEL/4);
    split_kernel<<<(DMODEL*DMODEL/4)/256, 256>>>(Wq, whi + 0*1048576, wlo + 0*1048576, DMODEL*DMODEL/4);
    split_kernel<<<(DMODEL*DMODEL/4)/256, 256>>>(Wk, whi + 1*1048576, wlo + 1*1048576, DMODEL*DMODEL/4);
    split_kernel<<<(DMODEL*DMODEL/4)/256, 256>>>(Wv, whi + 2*1048576, wlo + 2*1048576, DMODEL*DMODEL/4);
    split_kernel<<<(DMODEL*DMODEL/4)/256, 256>>>(Wo, whi + 3*1048576, wlo + 3*1048576, DMODEL*DMODEL/4);

    // fused QKV projection (z = 0/1/2)
    gemm_hmma<1><<<dim3(DMODEL/128, MTOT/128, 3), 256, GSMEM>>>(
        xhi, xlo, whi, wlo, bq, bk, bv, pq, pk, pv);

    // rope + split q/k, split v
    rope_split<<<(BATCH*NHEAD*SEQ*(HDIM/2))/256, 256>>>(pq, pk, qhi, qlo, khi, klo);
    split_kernel<<<(BATCH*NHEAD*SEQ*HDIM/4)/256, 256>>>(pv, vhi, vlo, BATCH*NHEAD*SEQ*HDIM/4);

    // attention (128-row Q tiles, 8 warps)
    attn_hmma<<<dim3(SEQ/128, BATCH*NHEAD), 256, ASMEM>>>(
        qhi, qlo, khi, klo, vhi, vlo, pctx);

    // output projection
    split_kernel<<<(MTOT*DMODEL/4)/256, 256>>>(pctx, chi, clo, MTOT*DMODEL/4);
    gemm_hmma<0><<<dim3(DMODEL/128, MTOT/128, 1), 256, GSMEM>>>(
        chi, clo, whi + 3*1048576, wlo + 3*1048576, bo, bo, bo, out, out, out);
}

// round 7
// speedup vs baseline: 1.3524x; 1.3407x over previous
#include <cuda_runtime.h>
#include <cuda_fp16.h>
#include <math.h>
#include <cstdint>

// Problem constants (fixed by the reference)
#define BATCH 4
#define SEQ   2048
#define DMODEL 1024
#define NHEAD 16
#define HDIM  64
#define MTOT  (BATCH*SEQ)

typedef __half f16;

// ---------------------------------------------------------------------------
// Scratch (device globals)
// ---------------------------------------------------------------------------
__device__ float g_q[BATCH*NHEAD*SEQ*HDIM];   // [B,H,S,HD] f32
__device__ float g_k[BATCH*NHEAD*SEQ*HDIM];
__device__ float g_v[BATCH*NHEAD*SEQ*HDIM];
__device__ float g_ctx[MTOT*DMODEL];          // [B,S,D] f32

__device__ f16 g_xh[MTOT*DMODEL];             // X split hi/lo
__device__ f16 g_xl[MTOT*DMODEL];
__device__ f16 g_wh[4*DMODEL*DMODEL];         // packed Wq,Wk,Wv,Wo (single fp16)
__device__ f16 g_ch[MTOT*DMODEL];             // ctx split
__device__ f16 g_cl[MTOT*DMODEL];

__device__ f16 g_qh[BATCH*NHEAD*SEQ*HDIM];    // post-rope splits
__device__ f16 g_ql[BATCH*NHEAD*SEQ*HDIM];
__device__ f16 g_kh[BATCH*NHEAD*SEQ*HDIM];
__device__ f16 g_kl[BATCH*NHEAD*SEQ*HDIM];
__device__ f16 g_vh[BATCH*NHEAD*SEQ*HDIM];
__device__ f16 g_vl[BATCH*NHEAD*SEQ*HDIM];

// ---------------------------------------------------------------------------
// Helpers
// ---------------------------------------------------------------------------
__device__ __forceinline__ uint32_t smem_u32(const void* p) {
    uint32_t a;
    asm("{ .reg .u64 t; cvta.to.shared.u64 t, %1; cvt.u32.u64 %0, t; }"
        : "=r"(a) : "l"(p));
    return a;
}
__device__ __forceinline__ void cp16(uint32_t dst, const void* src) {
    asm volatile("cp.async.cg.shared.global [%0], [%1], 16;" :: "r"(dst), "l"(src));
}
__device__ __forceinline__ void cp_commit() {
    asm volatile("cp.async.commit_group;" ::: "memory");
}
__device__ __forceinline__ void cp_wait2() {
    asm volatile("cp.async.wait_group 2;" ::: "memory");
}
__device__ __forceinline__ void ldsm4(uint32_t* r, uint32_t addr) {
    asm volatile("ldmatrix.sync.aligned.m8n8.x4.shared.b16 {%0,%1,%2,%3}, [%4];"
                 : "=r"(r[0]), "=r"(r[1]), "=r"(r[2]), "=r"(r[3]) : "r"(addr));
}
__device__ __forceinline__ void ldsm4t(uint32_t* r, uint32_t addr) {
    asm volatile("ldmatrix.sync.aligned.m8n8.x4.trans.shared.b16 {%0,%1,%2,%3}, [%4];"
                 : "=r"(r[0]), "=r"(r[1]), "=r"(r[2]), "=r"(r[3]) : "r"(addr));
}
__device__ __forceinline__ void mma_f16(float* c, const uint32_t* a, const uint32_t* b) {
    asm volatile(
        "mma.sync.aligned.m16n8k16.row.col.f32.f16.f16.f32 "
        "{%0,%1,%2,%3}, {%4,%5,%6,%7}, {%8,%9}, {%0,%1,%2,%3};"
        : "+f"(c[0]), "+f"(c[1]), "+f"(c[2]), "+f"(c[3])
        : "r"(a[0]), "r"(a[1]), "r"(a[2]), "r"(a[3]), "r"(b[0]), "r"(b[1]));
}
__device__ __forceinline__ uint32_t pack_f16(float lo, float hi) {
    uint32_t r;
    asm("cvt.rn.f16x2.f32 %0, %1, %2;" : "=r"(r) : "f"(hi), "f"(lo));
    return r;
}

// ---------------------------------------------------------------------------
// fp32 -> fp16 hi/lo split, and plain fp32 -> fp16 convert
// ---------------------------------------------------------------------------
__global__ void split2_kernel(const float* __restrict__ x,
                              f16* __restrict__ hi, f16* __restrict__ lo, int n4)
{
    int i = blockIdx.x * blockDim.x + threadIdx.x;
    if (i >= n4) return;
    float4 v = ((const float4*)x)[i];
    f16 h0 = __float2half(v.x), h1 = __float2half(v.y);
    f16 h2 = __float2half(v.z), h3 = __float2half(v.w);
    f16 l0 = __float2half(v.x - __half2float(h0));
    f16 l1 = __float2half(v.y - __half2float(h1));
    f16 l2 = __float2half(v.z - __half2float(h2));
    f16 l3 = __float2half(v.w - __half2float(h3));
    ((__half2*)hi)[2*i]   = __halves2half2(h0, h1);
    ((__half2*)hi)[2*i+1] = __halves2half2(h2, h3);
    ((__half2*)lo)[2*i]   = __halves2half2(l0, l1);
    ((__half2*)lo)[2*i+1] = __halves2half2(l2, l3);
}

__global__ void cvt_kernel(const float* __restrict__ x, f16* __restrict__ y, int n4)
{
    int i = blockIdx.x * blockDim.x + threadIdx.x;
    if (i >= n4) return;
    float4 v = ((const float4*)x)[i];
    ((__half2*)y)[2*i]   = __halves2half2(__float2half(v.x), __float2half(v.y));
    ((__half2*)y)[2*i+1] = __halves2half2(__float2half(v.z), __float2half(v.w));
}

// ---------------------------------------------------------------------------
// HMMA GEMM: C[m,n] = sum_k A[m,k]*W[n,k] + bias[n]
// A = fp16 hi+lo (2 products), W = single fp16. f32 accum.
// Tiles: 128x128x32, 8 warps (2M x 4N), warp tile 64x32, 3-stage cp.async.
// MODE 0: row-major out. MODE 1: scatter to [B,H,S,HD], z selects q/k/v.
// ---------------------------------------------------------------------------
#define GSTRIDE 40                        // fp16 per smem row (32+8 pad)
#define GTILE_B (128*GSTRIDE*2)           // 10240 bytes per tile
#define GSTAGE_B (3*GTILE_B)              // Ah, Al, W
#define GSTAGES 3
#define GSMEM (GSTAGES*GSTAGE_B)          // 92160

__device__ __forceinline__ void g_load_stage(
    uint32_t smb, int s, int kt, int m0, int n0,
    const f16* Ah, const f16* Al, const f16* W, int tid)
{
    uint32_t base = smb + s * GSTAGE_B;
    int kc = kt * 32;
    // 3 tiles x 128 rows x 4 chunks = 1536 transfers / 256 threads
#pragma unroll
    for (int i = 0; i < 6; ++i) {
        int t = tid + i * 256;
        int tile = t >> 9;
        int r = (t >> 2) & 127;
        int c = t & 3;
        const f16* src;
        if      (tile == 0) src = Ah + (size_t)(m0 + r) * DMODEL + kc + c * 8;
        else if (tile == 1) src = Al + (size_t)(m0 + r) * DMODEL + kc + c * 8;
        else                src = W  + (size_t)(n0 + r) * DMODEL + kc + c * 8;
        cp16(base + tile * GTILE_B + r * (GSTRIDE*2) + c * 16, src);
    }
    cp_commit();
}

template<int MODE>
__global__ void __launch_bounds__(256, 2)
gemm_hmma(const f16* __restrict__ Ah, const f16* __restrict__ Al,
          const f16* __restrict__ Wp,
          const float* __restrict__ b0, const float* __restrict__ b1,
          const float* __restrict__ b2,
          float* __restrict__ dq, float* __restrict__ dk, float* __restrict__ dv)
{
    extern __shared__ char smc[];
    const uint32_t smb = smem_u32(smc);
    const int tid  = threadIdx.x;
    const int warp = tid >> 5, lane = tid & 31;
    const int z  = blockIdx.z;
    const int m0 = blockIdx.y * 128;
    const int n0 = blockIdx.x * 128;
    const int wm = (warp & 1) * 64;
    const int wn = (warp >> 1) * 32;

    const f16* W = Wp + ((size_t)z << 20);
    const float* bias = (z == 0) ? b0 : (z == 1) ? b1 : b2;
    float* dst        = (z == 0) ? dq : (z == 1) ? dk : dv;

    float acc[4][4][4];
#pragma unroll
    for (int i = 0; i < 4; ++i)
#pragma unroll
        for (int j = 0; j < 4; ++j)
#pragma unroll
            for (int c = 0; c < 4; ++c) acc[i][j][c] = 0.f;

    g_load_stage(smb, 0, 0, m0, n0, Ah, Al, W, tid);
    g_load_stage(smb, 1, 1, m0, n0, Ah, Al, W, tid);
    g_load_stage(smb, 2, 2, m0, n0, Ah, Al, W, tid);

    const int arow = lane & 15, akh = lane >> 4;
    const int brow = lane & 7, bkh = (lane >> 3) & 1, bpr = lane >> 4;

    int stage = 0;
    for (int kt = 0; kt < 32; ++kt) {
        uint32_t base = smb + stage * GSTAGE_B;
        cp_wait2();
        __syncthreads();

#pragma unroll
        for (int kk = 0; kk < 2; ++kk) {
            uint32_t ah[4][4], al[4][4];
#pragma unroll
            for (int mt = 0; mt < 4; ++mt) {
                uint32_t ad = base + (wm + mt*16 + arow) * (GSTRIDE*2)
                                   + (kk*16 + akh*8) * 2;
                ldsm4(ah[mt], ad);
                ldsm4(al[mt], ad + GTILE_B);
            }
            uint32_t bh[4][2];
#pragma unroll
            for (int p = 0; p < 2; ++p) {
                uint32_t bd = base + 2*GTILE_B
                            + (wn + p*16 + bpr*8 + brow) * (GSTRIDE*2)
                            + (kk*16 + bkh*8) * 2;
                uint32_t r[4];
                ldsm4(r, bd);
                bh[2*p][0]=r[0]; bh[2*p][1]=r[1]; bh[2*p+1][0]=r[2]; bh[2*p+1][1]=r[3];
            }
#pragma unroll
            for (int mt = 0; mt < 4; ++mt)
#pragma unroll
                for (int nt = 0; nt < 4; ++nt) {
                    mma_f16(acc[mt][nt], ah[mt], bh[nt]);
                    mma_f16(acc[mt][nt], al[mt], bh[nt]);
                }
        }
        __syncthreads();
        if (kt + 3 < 32) g_load_stage(smb, stage, kt + 3, m0, n0, Ah, Al, W, tid);
        else             cp_commit();
        stage = (stage + 1 == GSTAGES) ? 0 : stage + 1;
    }

    // epilogue
    const int gid = lane >> 2, tig = lane & 3;
#pragma unroll
    for (int mt = 0; mt < 4; ++mt) {
#pragma unroll
        for (int nt = 0; nt < 4; ++nt) {
#pragma unroll
            for (int half = 0; half < 2; ++half) {
                int mrow = m0 + wm + mt*16 + gid + half*8;
                int ncol = n0 + wn + nt*8 + tig*2;
                float2 v;
                v.x = acc[mt][nt][half*2]   + bias[ncol];
                v.y = acc[mt][nt][half*2+1] + bias[ncol+1];
                if (MODE == 0) {
                    *(float2*)&dst[(size_t)mrow * DMODEL + ncol] = v;
                } else {
                    int h  = ncol >> 6, hd = ncol & 63;
                    int bb = mrow >> 11, s = mrow & (SEQ-1);
                    *(float2*)&dst[(((size_t)(bb*NHEAD + h))*SEQ + s)*HDIM + hd] = v;
                }
            }
        }
    }
}

// ---------------------------------------------------------------------------
// RoPE + split to fp16 hi/lo (reference: "c"=sin half, "s"=cos half)
// ---------------------------------------------------------------------------
__global__ void rope_split(const float* __restrict__ q, const float* __restrict__ k,
                           f16* __restrict__ qhi, f16* __restrict__ qlo,
                           f16* __restrict__ khi, f16* __restrict__ klo)
{
    int idx = blockIdx.x*blockDim.x + threadIdx.x;
    if (idx >= BATCH*NHEAD*SEQ*(HDIM/2)) return;
    int j  = idx & 31;
    int s  = (idx >> 5) & (SEQ-1);
    int bh = idx >> 16;

    float inv = powf(10000.f, -(float)j / 32.f);
    float ang = (float)s * inv;
    float sn, cs;
    sincosf(ang, &sn, &cs);

    size_t base = ((size_t)bh*SEQ + s)*HDIM;
    {
        float x1 = q[base+j], x2 = q[base+j+32];
        float y1 = x1*sn - x2*cs, y2 = x2*sn + x1*cs;
        f16 h1 = __float2half(y1), h2 = __float2half(y2);
        qhi[base+j] = h1; qhi[base+j+32] = h2;
        qlo[base+j]    = __float2half(y1 - __half2float(h1));
        qlo[base+j+32] = __float2half(y2 - __half2float(h2));
    }
    {
        float x1 = k[base+j], x2 = k[base+j+32];
        float y1 = x1*sn - x2*cs, y2 = x2*sn + x1*cs;
        f16 h1 = __float2half(y1), h2 = __float2half(y2);
        khi[base+j] = h1; khi[base+j+32] = h2;
        klo[base+j]    = __float2half(y1 - __half2float(h1));
        klo[base+j+32] = __float2half(y2 - __half2float(h2));
    }
}

// ---------------------------------------------------------------------------
// Flash attention on HMMA fp16. 128-row Q tiles, 8 warps (16 rows each),
// 3-stage cp.async ring of 64-row K/V tiles.
// QK^T: fp16x3 (exact to 2^-22).  PV: P single fp16, V hi+lo (2 products).
// ---------------------------------------------------------------------------
#define ASTRIDE 72                        // fp16 per smem row (64+8 pad)
#define ATILE_B (64*ASTRIDE*2)            // 9216 bytes (64-row tile)
#define AQTILE_B (128*ASTRIDE*2)          // 18432 bytes (128-row Q tile)
#define AKV_STAGE (4*ATILE_B)             // Kh,Kl,Vh,Vl
#define ASTAGES 3
#define ASMEM (2*AQTILE_B + ASTAGES*AKV_STAGE)   // 147456

__device__ __forceinline__ void a_load_kv(
    uint32_t smb, int s, int k0, const f16* kh, const f16* kl,
    const f16* vh, const f16* vl, int tid)
{
    uint32_t base = smb + 2*AQTILE_B + s * AKV_STAGE;
#pragma unroll
    for (int i = 0; i < 8; ++i) {
        int t = tid + i * 256;
        int tile = t >> 9;
        int r = (t >> 3) & 63;
        int c = t & 7;
        const f16* src;
        if      (tile == 0) src = kh + (size_t)(k0 + r) * HDIM + c * 8;
        else if (tile == 1) src = kl + (size_t)(k0 + r) * HDIM + c * 8;
        else if (tile == 2) src = vh + (size_t)(k0 + r) * HDIM + c * 8;
        else                src = vl + (size_t)(k0 + r) * HDIM + c * 8;
        cp16(base + tile * ATILE_B + r * (ASTRIDE*2) + c * 16, src);
    }
    cp_commit();
}

__global__ void __launch_bounds__(256, 1)
attn_hmma(const f16* __restrict__ Qh, const f16* __restrict__ Ql,
          const f16* __restrict__ Kh, const f16* __restrict__ Kl,
          const f16* __restrict__ Vh, const f16* __restrict__ Vl,
          float* __restrict__ ctx)
{
    extern __shared__ char smc[];
    const uint32_t smb = smem_u32(smc);
    const int tid = threadIdx.x;
    const int warp = tid >> 5, lane = tid & 31;
    const int q0 = blockIdx.x * 128;
    const int bh = blockIdx.y;

    const f16* qhg = Qh + ((size_t)bh*SEQ + q0)*HDIM;
    const f16* qlg = Ql + ((size_t)bh*SEQ + q0)*HDIM;
    const f16* khg = Kh + (size_t)bh*SEQ*HDIM;
    const f16* klg = Kl + (size_t)bh*SEQ*HDIM;
    const f16* vhg = Vh + (size_t)bh*SEQ*HDIM;
    const f16* vlg = Vl + (size_t)bh*SEQ*HDIM;

    // Q tiles: 2 tiles x 128 rows x 8 chunks = 2048 transfers / 256 threads
#pragma unroll
    for (int i = 0; i < 8; ++i) {
        int t = tid + i * 256;
        int tile = t >> 10;
        int r = (t >> 3) & 127;
        int c = t & 7;
        const f16* src = (tile ? qlg : qhg) + (size_t)r * HDIM + c * 8;
        cp16(smb + tile * AQTILE_B + r * (ASTRIDE*2) + c * 16, src);
    }
    a_load_kv(smb, 0, 0,   khg, klg, vhg, vlg, tid);
    a_load_kv(smb, 1, 64,  khg, klg, vhg, vlg, tid);
    a_load_kv(smb, 2, 128, khg, klg, vhg, vlg, tid);

    const int gid = lane >> 2, tig = lane & 3;
    const int arow = lane & 15, akh = lane >> 4;
    const int brow = lane & 7, bkh = (lane >> 3) & 1, bpr = lane >> 4;

    uint32_t qh[4][4], ql[4][4];
    float o[8][4];
#pragma unroll
    for (int nt = 0; nt < 8; ++nt)
#pragma unroll
        for (int c = 0; c < 4; ++c) o[nt][c] = 0.f;
    float mrow0 = -INFINITY, mrow1 = -INFINITY, lrow0 = 0.f, lrow1 = 0.f;

    int stage = 0;
    for (int kt = 0; kt < SEQ/64; ++kt) {
        uint32_t base = smb + 2*AQTILE_B + stage * AKV_STAGE;
        cp_wait2();
        __syncthreads();

        if (kt == 0) {
#pragma unroll
            for (int kx = 0; kx < 4; ++kx) {
                uint32_t ad = smb + (warp*16 + arow) * (ASTRIDE*2) + (kx*16 + akh*8) * 2;
                ldsm4(qh[kx], ad);
                ldsm4(ql[kx], ad + AQTILE_B);
            }
        }

        // S = Q K^T  (fp16x3)
        float s[8][4];
#pragma unroll
        for (int nt = 0; nt < 8; ++nt)
#pragma unroll
            for (int c = 0; c < 4; ++c) s[nt][c] = 0.f;

#pragma unroll
        for (int kx = 0; kx < 4; ++kx) {
            uint32_t kbh[8][2], kbl[8][2];
#pragma unroll
            for (int p = 0; p < 4; ++p) {
                uint32_t bd = base + (p*16 + bpr*8 + brow) * (ASTRIDE*2)
                            + (kx*16 + bkh*8) * 2;
                uint32_t r[4];
                ldsm4(r, bd);
                kbh[2*p][0]=r[0]; kbh[2*p][1]=r[1]; kbh[2*p+1][0]=r[2]; kbh[2*p+1][1]=r[3];
                ldsm4(r, bd + ATILE_B);
                kbl[2*p][0]=r[0]; kbl[2*p][1]=r[1]; kbl[2*p+1][0]=r[2]; kbl[2*p+1][1]=r[3];
            }
#pragma unroll
            for (int nt = 0; nt < 8; ++nt) {
                mma_f16(s[nt], qh[kx], kbh[nt]);
                mma_f16(s[nt], qh[kx], kbl[nt]);
                mma_f16(s[nt], ql[kx], kbh[nt]);
            }
        }

        // online softmax (scale 1/8); rows gid (c0,c1) and gid+8 (c2,c3)
        float mx0 = -INFINITY, mx1 = -INFINITY;
#pragma unroll
        for (int nt = 0; nt < 8; ++nt) {
#pragma unroll
            for (int c = 0; c < 4; ++c) s[nt][c] *= 0.125f;
            mx0 = fmaxf(mx0, fmaxf(s[nt][0], s[nt][1]));
            mx1 = fmaxf(mx1, fmaxf(s[nt][2], s[nt][3]));
        }
        mx0 = fmaxf(mx0, __shfl_xor_sync(0xffffffffu, mx0, 1));
        mx0 = fmaxf(mx0, __shfl_xor_sync(0xffffffffu, mx0, 2));
        mx1 = fmaxf(mx1, __shfl_xor_sync(0xffffffffu, mx1, 1));
        mx1 = fmaxf(mx1, __shfl_xor_sync(0xffffffffu, mx1, 2));
        float mn0 = fmaxf(mrow0, mx0), mn1 = fmaxf(mrow1, mx1);
        float al0 = __expf(mrow0 - mn0), al1 = __expf(mrow1 - mn1);
        mrow0 = mn0; mrow1 = mn1;

        float ls0 = 0.f, ls1 = 0.f;
#pragma unroll
        for (int nt = 0; nt < 8; ++nt) {
            s[nt][0] = __expf(s[nt][0] - mn0);
            s[nt][1] = __expf(s[nt][1] - mn0);
            s[nt][2] = __expf(s[nt][2] - mn1);
            s[nt][3] = __expf(s[nt][3] - mn1);
            ls0 += s[nt][0] + s[nt][1];
            ls1 += s[nt][2] + s[nt][3];
        }
        ls0 += __shfl_xor_sync(0xffffffffu, ls0, 1);
        ls0 += __shfl_xor_sync(0xffffffffu, ls0, 2);
        ls1 += __shfl_xor_sync(0xffffffffu, ls1, 1);
        ls1 += __shfl_xor_sync(0xffffffffu, ls1, 2);
        lrow0 = lrow0 * al0 + ls0;
        lrow1 = lrow1 * al1 + ls1;

#pragma unroll
        for (int nt = 0; nt < 8; ++nt) {
            o[nt][0] *= al0; o[nt][1] *= al0;
            o[nt][2] *= al1; o[nt][3] *= al1;
        }

        // pack P into A-fragments (single fp16; rel err ~2^-11)
        uint32_t ap[4][4];
#pragma unroll
        for (int j = 0; j < 4; ++j) {
#pragma unroll
            for (int rr = 0; rr < 4; ++rr) {
                int nt = 2*j + (rr >> 1);
                ap[j][rr] = pack_f16(s[nt][(rr & 1)*2], s[nt][(rr & 1)*2 + 1]);
            }
        }

        // O += P V  (V hi+lo, 2 products)
#pragma unroll
        for (int j = 0; j < 4; ++j) {
            uint32_t vbh[8][2], vbl[8][2];
#pragma unroll
            for (int p = 0; p < 4; ++p) {
                uint32_t vd = base + 2*ATILE_B
                            + (j*16 + (lane & 15)) * (ASTRIDE*2)
                            + (p*16 + (lane >> 4)*8) * 2;
                uint32_t r[4];
                ldsm4t(r, vd);
                vbh[2*p][0]=r[0]; vbh[2*p][1]=r[1]; vbh[2*p+1][0]=r[2]; vbh[2*p+1][1]=r[3];
                ldsm4t(r, vd + ATILE_B);
                vbl[2*p][0]=r[0]; vbl[2*p][1]=r[1]; vbl[2*p+1][0]=r[2]; vbl[2*p+1][1]=r[3];
            }
#pragma unroll
            for (int nt = 0; nt < 8; ++nt) {
                mma_f16(o[nt], ap[j], vbh[nt]);
                mma_f16(o[nt], ap[j], vbl[nt]);
            }
        }

        __syncthreads();
        if (kt + 3 < SEQ/64) a_load_kv(smb, stage, (kt+3)*64, khg, klg, vhg, vlg, tid);
        else                 cp_commit();
        stage = (stage + 1 == ASTAGES) ? 0 : stage + 1;
    }

    // write ctx
    const int b = bh >> 4, h = bh & 15;
    float il0 = 1.f / lrow0, il1 = 1.f / lrow1;
    int r0g = q0 + warp*16 + gid;
#pragma unroll
    for (int nt = 0; nt < 8; ++nt) {
        int col = h*HDIM + nt*8 + tig*2;
        float2 v0; v0.x = o[nt][0]*il0; v0.y = o[nt][1]*il0;
        float2 v1; v1.x = o[nt][2]*il1; v1.y = o[nt][3]*il1;
        *(float2*)&ctx[((size_t)(b*SEQ + r0g))*DMODEL + col] = v0;
        *(float2*)&ctx[((size_t)(b*SEQ + r0g + 8))*DMODEL + col] = v1;
    }
}

// ---------------------------------------------------------------------------
// Launch
// ---------------------------------------------------------------------------
extern "C" void kernel_launch(void* const* d_in, const int* in_sizes, int n_in,
                              void* d_out, int out_size)
{
    const float* X  = (const float*)d_in[0];
    const float* Wq = (const float*)d_in[1];
    const float* bq = (const float*)d_in[2];
    const float* Wk = (const float*)d_in[3];
    const float* bk = (const float*)d_in[4];
    const float* Wv = (const float*)d_in[5];
    const float* bv = (const float*)d_in[6];
    const float* Wo = (const float*)d_in[7];
    const float* bo = (const float*)d_in[8];
    float* out = (float*)d_out;

    float *pq, *pk, *pv, *pctx;
    f16 *xh, *xl, *wh, *ch, *cl;
    f16 *qh, *ql, *kh, *kl, *vh, *vl;
    cudaGetSymbolAddress((void**)&pq,   g_q);
    cudaGetSymbolAddress((void**)&pk,   g_k);
    cudaGetSymbolAddress((void**)&pv,   g_v);
    cudaGetSymbolAddress((void**)&pctx, g_ctx);
    cudaGetSymbolAddress((void**)&xh,   g_xh);
    cudaGetSymbolAddress((void**)&xl,   g_xl);
    cudaGetSymbolAddress((void**)&wh,   g_wh);
    cudaGetSymbolAddress((void**)&ch,   g_ch);
    cudaGetSymbolAddress((void**)&cl,   g_cl);
    cudaGetSymbolAddress((void**)&qh,   g_qh);
    cudaGetSymbolAddress((void**)&ql,   g_ql);
    cudaGetSymbolAddress((void**)&kh,   g_kh);
    cudaGetSymbolAddress((void**)&kl,   g_kl);
    cudaGetSymbolAddress((void**)&vh,   g_vh);
    cudaGetSymbolAddress((void**)&vl,   g_vl);

    cudaFuncSetAttribute(gemm_hmma<0>, cudaFuncAttributeMaxDynamicSharedMemorySize, GSMEM);
    cudaFuncSetAttribute(gemm_hmma<1>, cudaFuncAttributeMaxDynamicSharedMemorySize, GSMEM);
    cudaFuncSetAttribute(attn_hmma, cudaFuncAttributeMaxDynamicSharedMemorySize, ASMEM);

    // splits / converts
    split2_kernel<<<(MTOT*DMODEL/4)/256, 256>>>(X, xh, xl, MTOT*DMODEL/4);
    cvt_kernel<<<(DMODEL*DMODEL/4)/256, 256>>>(Wq, wh + 0*1048576, DMODEL*DMODEL/4);
    cvt_kernel<<<(DMODEL*DMODEL/4)/256, 256>>>(Wk, wh + 1*1048576, DMODEL*DMODEL/4);
    cvt_kernel<<<(DMODEL*DMODEL/4)/256, 256>>>(Wv, wh + 2*1048576, DMODEL*DMODEL/4);
    cvt_kernel<<<(DMODEL*DMODEL/4)/256, 256>>>(Wo, wh + 3*1048576, DMODEL*DMODEL/4);

    // fused QKV projection (z = 0/1/2)
    gemm_hmma<1><<<dim3(DMODEL/128, MTOT/128, 3), 256, GSMEM>>>(
        xh, xl, wh, bq, bk, bv, pq, pk, pv);

    // rope + split q/k, split v
    rope_split<<<(BATCH*NHEAD*SEQ*(HDIM/2))/256, 256>>>(pq, pk, qh, ql, kh, kl);
    split2_kernel<<<(BATCH*NHEAD*SEQ*HDIM/4)/256, 256>>>(pv, vh, vl, BATCH*NHEAD*SEQ*HDIM/4);

    // attention (128-row Q tiles, 8 warps)
    attn_hmma<<<dim3(SEQ/128, BATCH*NHEAD), 256, ASMEM>>>(
        qh, ql, kh, kl, vh, vl, pctx);

    // output projection
    split2_kernel<<<(MTOT*DMODEL/4)/256, 256>>>(pctx, ch, cl, MTOT*DMODEL/4);
    gemm_hmma<0><<<dim3(DMODEL/128, MTOT/128, 1), 256, GSMEM>>>(
        ch, cl, wh + 3*1048576, bo, bo, bo, out, out, out);
}

// round 8
// speedup vs baseline: 2.4500x; 1.8115x over previous
#include <cuda_runtime.h>
#include <cuda_fp16.h>
#include <math.h>
#include <cstdint>

// Problem constants (fixed by the reference)
#define BATCH 4
#define SEQ   2048
#define DMODEL 1024
#define NHEAD 16
#define HDIM  64
#define MTOT  (BATCH*SEQ)

typedef __half f16;

// ---------------------------------------------------------------------------
// Scratch (device globals)
// ---------------------------------------------------------------------------
__device__ float g_q[BATCH*NHEAD*SEQ*HDIM];   // [B,H,S,HD] f32
__device__ float g_k[BATCH*NHEAD*SEQ*HDIM];
__device__ float g_v[BATCH*NHEAD*SEQ*HDIM];
__device__ float g_ctx[MTOT*DMODEL];          // [B,S,D] f32

__device__ f16 g_xh[MTOT*DMODEL];             // X fp16
__device__ f16 g_wh[4*DMODEL*DMODEL];         // packed Wq,Wk,Wv,Wo fp16
__device__ f16 g_ch[MTOT*DMODEL];             // ctx fp16

__device__ f16 g_qh[BATCH*NHEAD*SEQ*HDIM];    // post-rope fp16
__device__ f16 g_kh[BATCH*NHEAD*SEQ*HDIM];
__device__ f16 g_vh[BATCH*NHEAD*SEQ*HDIM];

// ---------------------------------------------------------------------------
// Helpers
// ---------------------------------------------------------------------------
__device__ __forceinline__ uint32_t smem_u32(const void* p) {
    uint32_t a;
    asm("{ .reg .u64 t; cvta.to.shared.u64 t, %1; cvt.u32.u64 %0, t; }"
        : "=r"(a) : "l"(p));
    return a;
}
__device__ __forceinline__ void cp16(uint32_t dst, const void* src) {
    asm volatile("cp.async.cg.shared.global [%0], [%1], 16;" :: "r"(dst), "l"(src));
}
__device__ __forceinline__ void cp_commit() {
    asm volatile("cp.async.commit_group;" ::: "memory");
}
__device__ __forceinline__ void cp_wait2() {
    asm volatile("cp.async.wait_group 2;" ::: "memory");
}
__device__ __forceinline__ void ldsm4(uint32_t* r, uint32_t addr) {
    asm volatile("ldmatrix.sync.aligned.m8n8.x4.shared.b16 {%0,%1,%2,%3}, [%4];"
                 : "=r"(r[0]), "=r"(r[1]), "=r"(r[2]), "=r"(r[3]) : "r"(addr));
}
__device__ __forceinline__ void ldsm4t(uint32_t* r, uint32_t addr) {
    asm volatile("ldmatrix.sync.aligned.m8n8.x4.trans.shared.b16 {%0,%1,%2,%3}, [%4];"
                 : "=r"(r[0]), "=r"(r[1]), "=r"(r[2]), "=r"(r[3]) : "r"(addr));
}
__device__ __forceinline__ void mma_f16(float* c, const uint32_t* a, const uint32_t* b) {
    asm volatile(
        "mma.sync.aligned.m16n8k16.row.col.f32.f16.f16.f32 "
        "{%0,%1,%2,%3}, {%4,%5,%6,%7}, {%8,%9}, {%0,%1,%2,%3};"
        : "+f"(c[0]), "+f"(c[1]), "+f"(c[2]), "+f"(c[3])
        : "r"(a[0]), "r"(a[1]), "r"(a[2]), "r"(a[3]), "r"(b[0]), "r"(b[1]));
}
__device__ __forceinline__ uint32_t pack_f16(float lo, float hi) {
    uint32_t r;
    asm("cvt.rn.f16x2.f32 %0, %1, %2;" : "=r"(r) : "f"(hi), "f"(lo));
    return r;
}

// ---------------------------------------------------------------------------
// fp32 -> fp16 convert
// ---------------------------------------------------------------------------
__global__ void cvt_kernel(const float* __restrict__ x, f16* __restrict__ y, int n4)
{
    int i = blockIdx.x * blockDim.x + threadIdx.x;
    if (i >= n4) return;
    float4 v = ((const float4*)x)[i];
    ((__half2*)y)[2*i]   = __halves2half2(__float2half(v.x), __float2half(v.y));
    ((__half2*)y)[2*i+1] = __halves2half2(__float2half(v.z), __float2half(v.w));
}

// ---------------------------------------------------------------------------
// HMMA GEMM: C[m,n] = sum_k A[m,k]*W[n,k] + bias[n]   (single fp16, f32 acc)
// Tiles: 128x128x32, 8 warps (2M x 4N), warp tile 64x32, 3-stage cp.async.
// MODE 0: row-major out. MODE 1: scatter to [B,H,S,HD], z selects q/k/v.
// ---------------------------------------------------------------------------
#define GSTRIDE 40                        // fp16 per smem row (32+8 pad)
#define GTILE_B (128*GSTRIDE*2)           // 10240 bytes per tile
#define GSTAGE_B (2*GTILE_B)              // A, W
#define GSTAGES 3
#define GSMEM (GSTAGES*GSTAGE_B)          // 61440

__device__ __forceinline__ void g_load_stage(
    uint32_t smb, int s, int kt, int m0, int n0,
    const f16* A, const f16* W, int tid)
{
    uint32_t base = smb + s * GSTAGE_B;
    int kc = kt * 32;
    // 2 tiles x 128 rows x 4 chunks = 1024 transfers / 256 threads
#pragma unroll
    for (int i = 0; i < 4; ++i) {
        int t = tid + i * 256;
        int tile = t >> 9;
        int r = (t >> 2) & 127;
        int c = t & 3;
        const f16* src = (tile == 0) ? A + (size_t)(m0 + r) * DMODEL + kc + c * 8
                                     : W + (size_t)(n0 + r) * DMODEL + kc + c * 8;
        cp16(base + tile * GTILE_B + r * (GSTRIDE*2) + c * 16, src);
    }
    cp_commit();
}

template<int MODE>
__global__ void __launch_bounds__(256, 2)
gemm_hmma(const f16* __restrict__ A, const f16* __restrict__ Wp,
          const float* __restrict__ b0, const float* __restrict__ b1,
          const float* __restrict__ b2,
          float* __restrict__ dq, float* __restrict__ dk, float* __restrict__ dv)
{
    extern __shared__ char smc[];
    const uint32_t smb = smem_u32(smc);
    const int tid  = threadIdx.x;
    const int warp = tid >> 5, lane = tid & 31;
    const int z  = blockIdx.z;
    const int m0 = blockIdx.y * 128;
    const int n0 = blockIdx.x * 128;
    const int wm = (warp & 1) * 64;
    const int wn = (warp >> 1) * 32;

    const f16* W = Wp + ((size_t)z << 20);
    const float* bias = (z == 0) ? b0 : (z == 1) ? b1 : b2;
    float* dst        = (z == 0) ? dq : (z == 1) ? dk : dv;

    float acc[4][4][4];
#pragma unroll
    for (int i = 0; i < 4; ++i)
#pragma unroll
        for (int j = 0; j < 4; ++j)
#pragma unroll
            for (int c = 0; c < 4; ++c) acc[i][j][c] = 0.f;

    g_load_stage(smb, 0, 0, m0, n0, A, W, tid);
    g_load_stage(smb, 1, 1, m0, n0, A, W, tid);
    g_load_stage(smb, 2, 2, m0, n0, A, W, tid);

    const int arow = lane & 15, akh = lane >> 4;
    const int brow = lane & 7, bkh = (lane >> 3) & 1, bpr = lane >> 4;

    int stage = 0;
    for (int kt = 0; kt < 32; ++kt) {
        uint32_t base = smb + stage * GSTAGE_B;
        cp_wait2();
        __syncthreads();

#pragma unroll
        for (int kk = 0; kk < 2; ++kk) {
            uint32_t ah[4][4];
#pragma unroll
            for (int mt = 0; mt < 4; ++mt) {
                uint32_t ad = base + (wm + mt*16 + arow) * (GSTRIDE*2)
                                   + (kk*16 + akh*8) * 2;
                ldsm4(ah[mt], ad);
            }
            uint32_t bh[4][2];
#pragma unroll
            for (int p = 0; p < 2; ++p) {
                uint32_t bd = base + GTILE_B
                            + (wn + p*16 + bpr*8 + brow) * (GSTRIDE*2)
                            + (kk*16 + bkh*8) * 2;
                uint32_t r[4];
                ldsm4(r, bd);
                bh[2*p][0]=r[0]; bh[2*p][1]=r[1]; bh[2*p+1][0]=r[2]; bh[2*p+1][1]=r[3];
            }
#pragma unroll
            for (int mt = 0; mt < 4; ++mt)
#pragma unroll
                for (int nt = 0; nt < 4; ++nt)
                    mma_f16(acc[mt][nt], ah[mt], bh[nt]);
        }
        __syncthreads();
        if (kt + 3 < 32) g_load_stage(smb, stage, kt + 3, m0, n0, A, W, tid);
        else             cp_commit();
        stage = (stage + 1 == GSTAGES) ? 0 : stage + 1;
    }

    // epilogue
    const int gid = lane >> 2, tig = lane & 3;
#pragma unroll
    for (int mt = 0; mt < 4; ++mt) {
#pragma unroll
        for (int nt = 0; nt < 4; ++nt) {
#pragma unroll
            for (int half = 0; half < 2; ++half) {
                int mrow = m0 + wm + mt*16 + gid + half*8;
                int ncol = n0 + wn + nt*8 + tig*2;
                float2 v;
                v.x = acc[mt][nt][half*2]   + bias[ncol];
                v.y = acc[mt][nt][half*2+1] + bias[ncol+1];
                if (MODE == 0) {
                    *(float2*)&dst[(size_t)mrow * DMODEL + ncol] = v;
                } else {
                    int h  = ncol >> 6, hd = ncol & 63;
                    int bb = mrow >> 11, s = mrow & (SEQ-1);
                    *(float2*)&dst[(((size_t)(bb*NHEAD + h))*SEQ + s)*HDIM + hd] = v;
                }
            }
        }
    }
}

// ---------------------------------------------------------------------------
// RoPE -> single fp16 (reference: "c"=sin half, "s"=cos half)
// ---------------------------------------------------------------------------
__global__ void rope_cvt(const float* __restrict__ q, const float* __restrict__ k,
                         f16* __restrict__ qh, f16* __restrict__ kh)
{
    int idx = blockIdx.x*blockDim.x + threadIdx.x;
    if (idx >= BATCH*NHEAD*SEQ*(HDIM/2)) return;
    int j  = idx & 31;
    int s  = (idx >> 5) & (SEQ-1);
    int bh = idx >> 16;

    float inv = powf(10000.f, -(float)j / 32.f);
    float ang = (float)s * inv;
    float sn, cs;
    sincosf(ang, &sn, &cs);

    size_t base = ((size_t)bh*SEQ + s)*HDIM;
    {
        float x1 = q[base+j], x2 = q[base+j+32];
        qh[base+j]    = __float2half(x1*sn - x2*cs);
        qh[base+j+32] = __float2half(x2*sn + x1*cs);
    }
    {
        float x1 = k[base+j], x2 = k[base+j+32];
        kh[base+j]    = __float2half(x1*sn - x2*cs);
        kh[base+j+32] = __float2half(x2*sn + x1*cs);
    }
}

// ---------------------------------------------------------------------------
// Flash attention, single fp16 HMMA. 128-row Q tiles, 8 warps (16 rows each),
// 3-stage cp.async ring of 64-row K/V tiles. 2 CTAs/SM.
// ---------------------------------------------------------------------------
#define ASTRIDE 72                        // fp16 per smem row (64+8 pad)
#define ATILE_B (64*ASTRIDE*2)            // 9216 bytes (64-row tile)
#define AQTILE_B (128*ASTRIDE*2)          // 18432 bytes (128-row Q tile)
#define AKV_STAGE (2*ATILE_B)             // K, V
#define ASTAGES 3
#define ASMEM (AQTILE_B + ASTAGES*AKV_STAGE)   // 18432 + 55296 = 73728

__device__ __forceinline__ void a_load_kv(
    uint32_t smb, int s, int k0, const f16* kh, const f16* vh, int tid)
{
    uint32_t base = smb + AQTILE_B + s * AKV_STAGE;
    // 2 tiles x 64 rows x 8 chunks = 1024 transfers / 256 threads
#pragma unroll
    for (int i = 0; i < 4; ++i) {
        int t = tid + i * 256;
        int tile = t >> 9;
        int r = (t >> 3) & 63;
        int c = t & 7;
        const f16* src = (tile == 0) ? kh + (size_t)(k0 + r) * HDIM + c * 8
                                     : vh + (size_t)(k0 + r) * HDIM + c * 8;
        cp16(base + tile * ATILE_B + r * (ASTRIDE*2) + c * 16, src);
    }
    cp_commit();
}

__global__ void __launch_bounds__(256, 2)
attn_hmma(const f16* __restrict__ Qh, const f16* __restrict__ Kh,
          const f16* __restrict__ Vh, float* __restrict__ ctx)
{
    extern __shared__ char smc[];
    const uint32_t smb = smem_u32(smc);
    const int tid = threadIdx.x;
    const int warp = tid >> 5, lane = tid & 31;
    const int q0 = blockIdx.x * 128;
    const int bh = blockIdx.y;

    const f16* qhg = Qh + ((size_t)bh*SEQ + q0)*HDIM;
    const f16* khg = Kh + (size_t)bh*SEQ*HDIM;
    const f16* vhg = Vh + (size_t)bh*SEQ*HDIM;

    // Q tile: 128 rows x 8 chunks = 1024 transfers / 256 threads
#pragma unroll
    for (int i = 0; i < 4; ++i) {
        int t = tid + i * 256;
        int r = (t >> 3) & 127;
        int c = t & 7;
        cp16(smb + r * (ASTRIDE*2) + c * 16, qhg + (size_t)r * HDIM + c * 8);
    }
    a_load_kv(smb, 0, 0,   khg, vhg, tid);   // group 0 (incl. Q)
    a_load_kv(smb, 1, 64,  khg, vhg, tid);
    a_load_kv(smb, 2, 128, khg, vhg, tid);

    const int gid = lane >> 2, tig = lane & 3;
    const int arow = lane & 15, akh = lane >> 4;
    const int brow = lane & 7, bkh = (lane >> 3) & 1, bpr = lane >> 4;

    uint32_t qf[4][4];
    float o[8][4];
#pragma unroll
    for (int nt = 0; nt < 8; ++nt)
#pragma unroll
        for (int c = 0; c < 4; ++c) o[nt][c] = 0.f;
    float mrow0 = -INFINITY, mrow1 = -INFINITY, lrow0 = 0.f, lrow1 = 0.f;

    int stage = 0;
    for (int kt = 0; kt < SEQ/64; ++kt) {
        uint32_t base = smb + AQTILE_B + stage * AKV_STAGE;
        cp_wait2();
        __syncthreads();

        if (kt == 0) {
#pragma unroll
            for (int kx = 0; kx < 4; ++kx) {
                uint32_t ad = smb + (warp*16 + arow) * (ASTRIDE*2) + (kx*16 + akh*8) * 2;
                ldsm4(qf[kx], ad);
            }
        }

        // S = Q K^T
        float s[8][4];
#pragma unroll
        for (int nt = 0; nt < 8; ++nt)
#pragma unroll
            for (int c = 0; c < 4; ++c) s[nt][c] = 0.f;

#pragma unroll
        for (int kx = 0; kx < 4; ++kx) {
            uint32_t kb[8][2];
#pragma unroll
            for (int p = 0; p < 4; ++p) {
                uint32_t bd = base + (p*16 + bpr*8 + brow) * (ASTRIDE*2)
                            + (kx*16 + bkh*8) * 2;
                uint32_t r[4];
                ldsm4(r, bd);
                kb[2*p][0]=r[0]; kb[2*p][1]=r[1]; kb[2*p+1][0]=r[2]; kb[2*p+1][1]=r[3];
            }
#pragma unroll
            for (int nt = 0; nt < 8; ++nt)
                mma_f16(s[nt], qf[kx], kb[nt]);
        }

        // online softmax (scale 1/8); rows gid (c0,c1) and gid+8 (c2,c3)
        float mx0 = -INFINITY, mx1 = -INFINITY;
#pragma unroll
        for (int nt = 0; nt < 8; ++nt) {
#pragma unroll
            for (int c = 0; c < 4; ++c) s[nt][c] *= 0.125f;
            mx0 = fmaxf(mx0, fmaxf(s[nt][0], s[nt][1]));
            mx1 = fmaxf(mx1, fmaxf(s[nt][2], s[nt][3]));
        }
        mx0 = fmaxf(mx0, __shfl_xor_sync(0xffffffffu, mx0, 1));
        mx0 = fmaxf(mx0, __shfl_xor_sync(0xffffffffu, mx0, 2));
        mx1 = fmaxf(mx1, __shfl_xor_sync(0xffffffffu, mx1, 1));
        mx1 = fmaxf(mx1, __shfl_xor_sync(0xffffffffu, mx1, 2));
        float mn0 = fmaxf(mrow0, mx0), mn1 = fmaxf(mrow1, mx1);
        float al0 = __expf(mrow0 - mn0), al1 = __expf(mrow1 - mn1);
        mrow0 = mn0; mrow1 = mn1;

        float ls0 = 0.f, ls1 = 0.f;
#pragma unroll
        for (int nt = 0; nt < 8; ++nt) {
            s[nt][0] = __expf(s[nt][0] - mn0);
            s[nt][1] = __expf(s[nt][1] - mn0);
            s[nt][2] = __expf(s[nt][2] - mn1);
            s[nt][3] = __expf(s[nt][3] - mn1);
            ls0 += s[nt][0] + s[nt][1];
            ls1 += s[nt][2] + s[nt][3];
        }
        ls0 += __shfl_xor_sync(0xffffffffu, ls0, 1);
        ls0 += __shfl_xor_sync(0xffffffffu, ls0, 2);
        ls1 += __shfl_xor_sync(0xffffffffu, ls1, 1);
        ls1 += __shfl_xor_sync(0xffffffffu, ls1, 2);
        lrow0 = lrow0 * al0 + ls0;
        lrow1 = lrow1 * al1 + ls1;

#pragma unroll
        for (int nt = 0; nt < 8; ++nt) {
            o[nt][0] *= al0; o[nt][1] *= al0;
            o[nt][2] *= al1; o[nt][3] *= al1;
        }

        // pack P into A-fragments (single fp16)
        uint32_t ap[4][4];
#pragma unroll
        for (int j = 0; j < 4; ++j) {
#pragma unroll
            for (int rr = 0; rr < 4; ++rr) {
                int nt = 2*j + (rr >> 1);
                ap[j][rr] = pack_f16(s[nt][(rr & 1)*2], s[nt][(rr & 1)*2 + 1]);
            }
        }

        // O += P V
#pragma unroll
        for (int j = 0; j < 4; ++j) {
            uint32_t vb[8][2];
#pragma unroll
            for (int p = 0; p < 4; ++p) {
                uint32_t vd = base + ATILE_B
                            + (j*16 + (lane & 15)) * (ASTRIDE*2)
                            + (p*16 + (lane >> 4)*8) * 2;
                uint32_t r[4];
                ldsm4t(r, vd);
                vb[2*p][0]=r[0]; vb[2*p][1]=r[1]; vb[2*p+1][0]=r[2]; vb[2*p+1][1]=r[3];
            }
#pragma unroll
            for (int nt = 0; nt < 8; ++nt)
                mma_f16(o[nt], ap[j], vb[nt]);
        }

        __syncthreads();
        if (kt + 3 < SEQ/64) a_load_kv(smb, stage, (kt+3)*64, khg, vhg, tid);
        else                 cp_commit();
        stage = (stage + 1 == ASTAGES) ? 0 : stage + 1;
    }

    // write ctx
    const int b = bh >> 4, h = bh & 15;
    float il0 = 1.f / lrow0, il1 = 1.f / lrow1;
    int r0g = q0 + warp*16 + gid;
#pragma unroll
    for (int nt = 0; nt < 8; ++nt) {
        int col = h*HDIM + nt*8 + tig*2;
        float2 v0; v0.x = o[nt][0]*il0; v0.y = o[nt][1]*il0;
        float2 v1; v1.x = o[nt][2]*il1; v1.y = o[nt][3]*il1;
        *(float2*)&ctx[((size_t)(b*SEQ + r0g))*DMODEL + col] = v0;
        *(float2*)&ctx[((size_t)(b*SEQ + r0g + 8))*DMODEL + col] = v1;
    }
}

// ---------------------------------------------------------------------------
// Launch
// ---------------------------------------------------------------------------
extern "C" void kernel_launch(void* const* d_in, const int* in_sizes, int n_in,
                              void* d_out, int out_size)
{
    const float* X  = (const float*)d_in[0];
    const float* Wq = (const float*)d_in[1];
    const float* bq = (const float*)d_in[2];
    const float* Wk = (const float*)d_in[3];
    const float* bk = (const float*)d_in[4];
    const float* Wv = (const float*)d_in[5];
    const float* bv = (const float*)d_in[6];
    const float* Wo = (const float*)d_in[7];
    const float* bo = (const float*)d_in[8];
    float* out = (float*)d_out;

    float *pq, *pk, *pv, *pctx;
    f16 *xh, *wh, *ch, *qh, *kh, *vh;
    cudaGetSymbolAddress((void**)&pq,   g_q);
    cudaGetSymbolAddress((void**)&pk,   g_k);
    cudaGetSymbolAddress((void**)&pv,   g_v);
    cudaGetSymbolAddress((void**)&pctx, g_ctx);
    cudaGetSymbolAddress((void**)&xh,   g_xh);
    cudaGetSymbolAddress((void**)&wh,   g_wh);
    cudaGetSymbolAddress((void**)&ch,   g_ch);
    cudaGetSymbolAddress((void**)&qh,   g_qh);
    cudaGetSymbolAddress((void**)&kh,   g_kh);
    cudaGetSymbolAddress((void**)&vh,   g_vh);

    cudaFuncSetAttribute(gemm_hmma<0>, cudaFuncAttributeMaxDynamicSharedMemorySize, GSMEM);
    cudaFuncSetAttribute(gemm_hmma<1>, cudaFuncAttributeMaxDynamicSharedMemorySize, GSMEM);
    cudaFuncSetAttribute(attn_hmma, cudaFuncAttributeMaxDynamicSharedMemorySize, ASMEM);

    // converts
    cvt_kernel<<<(MTOT*DMODEL/4)/256, 256>>>(X, xh, MTOT*DMODEL/4);
    cvt_kernel<<<(DMODEL*DMODEL/4)/256, 256>>>(Wq, wh + 0*1048576, DMODEL*DMODEL/4);
    cvt_kernel<<<(DMODEL*DMODEL/4)/256, 256>>>(Wk, wh + 1*1048576, DMODEL*DMODEL/4);
    cvt_kernel<<<(DMODEL*DMODEL/4)/256, 256>>>(Wv, wh + 2*1048576, DMODEL*DMODEL/4);
    cvt_kernel<<<(DMODEL*DMODEL/4)/256, 256>>>(Wo, wh + 3*1048576, DMODEL*DMODEL/4);

    // fused QKV projection (z = 0/1/2)
    gemm_hmma<1><<<dim3(DMODEL/128, MTOT/128, 3), 256, GSMEM>>>(
        xh, wh, bq, bk, bv, pq, pk, pv);

    // rope -> fp16 q/k ; convert v
    rope_cvt<<<(BATCH*NHEAD*SEQ*(HDIM/2))/256, 256>>>(pq, pk, qh, kh);
    cvt_kernel<<<(BATCH*NHEAD*SEQ*HDIM/4)/256, 256>>>(pv, vh, BATCH*NHEAD*SEQ*HDIM/4);

    // attention (128-row Q tiles, 8 warps, 2 CTAs/SM)
    attn_hmma<<<dim3(SEQ/128, BATCH*NHEAD), 256, ASMEM>>>(qh, kh, vh, pctx);

    // output projection
    cvt_kernel<<<(MTOT*DMODEL/4)/256, 256>>>(pctx, ch, MTOT*DMODEL/4);
    gemm_hmma<0><<<dim3(DMODEL/128, MTOT/128, 1), 256, GSMEM>>>(
        ch, wh + 3*1048576, bo, bo, bo, out, out, out);
}

// round 9
// speedup vs baseline: 2.5488x; 1.0403x over previous
#include <cuda_runtime.h>
#include <cuda_fp16.h>
#include <math.h>
#include <cstdint>

// Problem constants (fixed by the reference)
#define BATCH 4
#define SEQ   2048
#define DMODEL 1024
#define NHEAD 16
#define HDIM  64
#define MTOT  (BATCH*SEQ)

typedef __half f16;

// ---------------------------------------------------------------------------
// Scratch (device globals)
// ---------------------------------------------------------------------------
__device__ float g_q[BATCH*NHEAD*SEQ*HDIM];   // [B,H,S,HD] f32 (pre-rope)
__device__ float g_k[BATCH*NHEAD*SEQ*HDIM];

__device__ f16 g_xh[MTOT*DMODEL];             // X fp16
__device__ f16 g_wh[4*DMODEL*DMODEL];         // packed Wq,Wk,Wv,Wo fp16
__device__ f16 g_ch[MTOT*DMODEL];             // ctx fp16 (written by attention)

__device__ f16 g_qh[BATCH*NHEAD*SEQ*HDIM];    // post-rope fp16
__device__ f16 g_kh[BATCH*NHEAD*SEQ*HDIM];
__device__ f16 g_vh[BATCH*NHEAD*SEQ*HDIM];    // written by projection epilogue

// ---------------------------------------------------------------------------
// Helpers
// ---------------------------------------------------------------------------
__device__ __forceinline__ uint32_t smem_u32(const void* p) {
    uint32_t a;
    asm("{ .reg .u64 t; cvta.to.shared.u64 t, %1; cvt.u32.u64 %0, t; }"
        : "=r"(a) : "l"(p));
    return a;
}
__device__ __forceinline__ void cp16(uint32_t dst, const void* src) {
    asm volatile("cp.async.cg.shared.global [%0], [%1], 16;" :: "r"(dst), "l"(src));
}
__device__ __forceinline__ void cp_commit() {
    asm volatile("cp.async.commit_group;" ::: "memory");
}
__device__ __forceinline__ void cp_wait2() {
    asm volatile("cp.async.wait_group 2;" ::: "memory");
}
__device__ __forceinline__ void ldsm4(uint32_t* r, uint32_t addr) {
    asm volatile("ldmatrix.sync.aligned.m8n8.x4.shared.b16 {%0,%1,%2,%3}, [%4];"
                 : "=r"(r[0]), "=r"(r[1]), "=r"(r[2]), "=r"(r[3]) : "r"(addr));
}
__device__ __forceinline__ void ldsm4t(uint32_t* r, uint32_t addr) {
    asm volatile("ldmatrix.sync.aligned.m8n8.x4.trans.shared.b16 {%0,%1,%2,%3}, [%4];"
                 : "=r"(r[0]), "=r"(r[1]), "=r"(r[2]), "=r"(r[3]) : "r"(addr));
}
__device__ __forceinline__ void mma_f16(float* c, const uint32_t* a, const uint32_t* b) {
    asm volatile(
        "mma.sync.aligned.m16n8k16.row.col.f32.f16.f16.f32 "
        "{%0,%1,%2,%3}, {%4,%5,%6,%7}, {%8,%9}, {%0,%1,%2,%3};"
        : "+f"(c[0]), "+f"(c[1]), "+f"(c[2]), "+f"(c[3])
        : "r"(a[0]), "r"(a[1]), "r"(a[2]), "r"(a[3]), "r"(b[0]), "r"(b[1]));
}
__device__ __forceinline__ uint32_t pack_f16(float lo, float hi) {
    uint32_t r;
    asm("cvt.rn.f16x2.f32 %0, %1, %2;" : "=r"(r) : "f"(hi), "f"(lo));
    return r;
}

// ---------------------------------------------------------------------------
// fp32 -> fp16 converts
// ---------------------------------------------------------------------------
__global__ void cvt_kernel(const float* __restrict__ x, f16* __restrict__ y, int n4)
{
    int i = blockIdx.x * blockDim.x + threadIdx.x;
    if (i >= n4) return;
    float4 v = ((const float4*)x)[i];
    ((__half2*)y)[2*i]   = __halves2half2(__float2half(v.x), __float2half(v.y));
    ((__half2*)y)[2*i+1] = __halves2half2(__float2half(v.z), __float2half(v.w));
}

// all four weights in one launch (blockIdx.y selects the matrix)
__global__ void cvtw_kernel(const float* __restrict__ w0, const float* __restrict__ w1,
                            const float* __restrict__ w2, const float* __restrict__ w3,
                            f16* __restrict__ y)
{
    int z = blockIdx.y;
    const float* x = (z == 0) ? w0 : (z == 1) ? w1 : (z == 2) ? w2 : w3;
    f16* dst = y + (size_t)z * DMODEL * DMODEL;
    int i = blockIdx.x * blockDim.x + threadIdx.x;   // over DMODEL*DMODEL/4
    float4 v = ((const float4*)x)[i];
    ((__half2*)dst)[2*i]   = __halves2half2(__float2half(v.x), __float2half(v.y));
    ((__half2*)dst)[2*i+1] = __halves2half2(__float2half(v.z), __float2half(v.w));
}

// ---------------------------------------------------------------------------
// HMMA GEMM: C[m,n] = sum_k A[m,k]*W[n,k] + bias[n]   (single fp16, f32 acc)
// Tiles: 128x128x32, 8 warps (2M x 4N), warp tile 64x32, 3-stage cp.async.
// MODE 0: f32 row-major out.
// MODE 1: scatter to [B,H,S,HD]; z=0/1 -> f32 q/k (rope input), z=2 -> fp16 v.
// ---------------------------------------------------------------------------
#define GSTRIDE 40                        // fp16 per smem row (32+8 pad)
#define GTILE_B (128*GSTRIDE*2)           // 10240 bytes per tile
#define GSTAGE_B (2*GTILE_B)              // A, W
#define GSTAGES 3
#define GSMEM (GSTAGES*GSTAGE_B)          // 61440

__device__ __forceinline__ void g_load_stage(
    uint32_t smb, int s, int kt, int m0, int n0,
    const f16* A, const f16* W, int tid)
{
    uint32_t base = smb + s * GSTAGE_B;
    int kc = kt * 32;
#pragma unroll
    for (int i = 0; i < 4; ++i) {
        int t = tid + i * 256;
        int tile = t >> 9;
        int r = (t >> 2) & 127;
        int c = t & 3;
        const f16* src = (tile == 0) ? A + (size_t)(m0 + r) * DMODEL + kc + c * 8
                                     : W + (size_t)(n0 + r) * DMODEL + kc + c * 8;
        cp16(base + tile * GTILE_B + r * (GSTRIDE*2) + c * 16, src);
    }
    cp_commit();
}

template<int MODE>
__global__ void __launch_bounds__(256, 2)
gemm_hmma(const f16* __restrict__ A, const f16* __restrict__ Wp,
          const float* __restrict__ b0, const float* __restrict__ b1,
          const float* __restrict__ b2,
          float* __restrict__ dq, float* __restrict__ dk,
          f16* __restrict__ dv16)
{
    extern __shared__ char smc[];
    const uint32_t smb = smem_u32(smc);
    const int tid  = threadIdx.x;
    const int warp = tid >> 5, lane = tid & 31;
    const int z  = blockIdx.z;
    const int m0 = blockIdx.y * 128;
    const int n0 = blockIdx.x * 128;
    const int wm = (warp & 1) * 64;
    const int wn = (warp >> 1) * 32;

    const f16* W = Wp + ((size_t)z << 20);
    const float* bias = (z == 0) ? b0 : (z == 1) ? b1 : b2;
    float* dstf       = (z == 0) ? dq : dk;

    float acc[4][4][4];
#pragma unroll
    for (int i = 0; i < 4; ++i)
#pragma unroll
        for (int j = 0; j < 4; ++j)
#pragma unroll
            for (int c = 0; c < 4; ++c) acc[i][j][c] = 0.f;

    g_load_stage(smb, 0, 0, m0, n0, A, W, tid);
    g_load_stage(smb, 1, 1, m0, n0, A, W, tid);
    g_load_stage(smb, 2, 2, m0, n0, A, W, tid);

    const int arow = lane & 15, akh = lane >> 4;
    const int brow = lane & 7, bkh = (lane >> 3) & 1, bpr = lane >> 4;

    int stage = 0;
    for (int kt = 0; kt < 32; ++kt) {
        uint32_t base = smb + stage * GSTAGE_B;
        cp_wait2();
        __syncthreads();

#pragma unroll
        for (int kk = 0; kk < 2; ++kk) {
            uint32_t ah[4][4];
#pragma unroll
            for (int mt = 0; mt < 4; ++mt) {
                uint32_t ad = base + (wm + mt*16 + arow) * (GSTRIDE*2)
                                   + (kk*16 + akh*8) * 2;
                ldsm4(ah[mt], ad);
            }
            uint32_t bh[4][2];
#pragma unroll
            for (int p = 0; p < 2; ++p) {
                uint32_t bd = base + GTILE_B
                            + (wn + p*16 + bpr*8 + brow) * (GSTRIDE*2)
                            + (kk*16 + bkh*8) * 2;
                uint32_t r[4];
                ldsm4(r, bd);
                bh[2*p][0]=r[0]; bh[2*p][1]=r[1]; bh[2*p+1][0]=r[2]; bh[2*p+1][1]=r[3];
            }
#pragma unroll
            for (int mt = 0; mt < 4; ++mt)
#pragma unroll
                for (int nt = 0; nt < 4; ++nt)
                    mma_f16(acc[mt][nt], ah[mt], bh[nt]);
        }
        __syncthreads();
        if (kt + 3 < 32) g_load_stage(smb, stage, kt + 3, m0, n0, A, W, tid);
        else             cp_commit();
        stage = (stage + 1 == GSTAGES) ? 0 : stage + 1;
    }

    // epilogue
    const int gid = lane >> 2, tig = lane & 3;
#pragma unroll
    for (int mt = 0; mt < 4; ++mt) {
#pragma unroll
        for (int nt = 0; nt < 4; ++nt) {
#pragma unroll
            for (int half = 0; half < 2; ++half) {
                int mrow = m0 + wm + mt*16 + gid + half*8;
                int ncol = n0 + wn + nt*8 + tig*2;
                float vx = acc[mt][nt][half*2]   + bias[ncol];
                float vy = acc[mt][nt][half*2+1] + bias[ncol+1];
                if (MODE == 0) {
                    float2 v; v.x = vx; v.y = vy;
                    *(float2*)&dstf[(size_t)mrow * DMODEL + ncol] = v;
                } else {
                    int h  = ncol >> 6, hd = ncol & 63;
                    int bb = mrow >> 11, s = mrow & (SEQ-1);
                    size_t off = (((size_t)(bb*NHEAD + h))*SEQ + s)*HDIM + hd;
                    if (z == 2) {
                        *(__half2*)&dv16[off] =
                            __halves2half2(__float2half(vx), __float2half(vy));
                    } else {
                        float2 v; v.x = vx; v.y = vy;
                        *(float2*)&dstf[off] = v;
                    }
                }
            }
        }
    }
}

// ---------------------------------------------------------------------------
// RoPE -> single fp16 (reference: "c"=sin half, "s"=cos half)
// ---------------------------------------------------------------------------
__global__ void rope_cvt(const float* __restrict__ q, const float* __restrict__ k,
                         f16* __restrict__ qh, f16* __restrict__ kh)
{
    int idx = blockIdx.x*blockDim.x + threadIdx.x;
    if (idx >= BATCH*NHEAD*SEQ*(HDIM/2)) return;
    int j  = idx & 31;
    int s  = (idx >> 5) & (SEQ-1);
    int bh = idx >> 16;

    float inv = powf(10000.f, -(float)j / 32.f);
    float ang = (float)s * inv;
    float sn, cs;
    sincosf(ang, &sn, &cs);

    size_t base = ((size_t)bh*SEQ + s)*HDIM;
    {
        float x1 = q[base+j], x2 = q[base+j+32];
        qh[base+j]    = __float2half(x1*sn - x2*cs);
        qh[base+j+32] = __float2half(x2*sn + x1*cs);
    }
    {
        float x1 = k[base+j], x2 = k[base+j+32];
        kh[base+j]    = __float2half(x1*sn - x2*cs);
        kh[base+j+32] = __float2half(x2*sn + x1*cs);
    }
}

// ---------------------------------------------------------------------------
// Flash attention, single fp16 HMMA. 128-row Q tiles, 8 warps (16 rows each),
// 3-stage cp.async ring of 64-row K/V tiles. 2 CTAs/SM. fp16 ctx output.
// ---------------------------------------------------------------------------
#define ASTRIDE 72                        // fp16 per smem row (64+8 pad)
#define ATILE_B (64*ASTRIDE*2)            // 9216 bytes (64-row tile)
#define AQTILE_B (128*ASTRIDE*2)          // 18432 bytes (128-row Q tile)
#define AKV_STAGE (2*ATILE_B)             // K, V
#define ASTAGES 3
#define ASMEM (AQTILE_B + ASTAGES*AKV_STAGE)   // 73728

__device__ __forceinline__ void a_load_kv(
    uint32_t smb, int s, int k0, const f16* kh, const f16* vh, int tid)
{
    uint32_t base = smb + AQTILE_B + s * AKV_STAGE;
#pragma unroll
    for (int i = 0; i < 4; ++i) {
        int t = tid + i * 256;
        int tile = t >> 9;
        int r = (t >> 3) & 63;
        int c = t & 7;
        const f16* src = (tile == 0) ? kh + (size_t)(k0 + r) * HDIM + c * 8
                                     : vh + (size_t)(k0 + r) * HDIM + c * 8;
        cp16(base + tile * ATILE_B + r * (ASTRIDE*2) + c * 16, src);
    }
    cp_commit();
}

__global__ void __launch_bounds__(256, 2)
attn_hmma(const f16* __restrict__ Qh, const f16* __restrict__ Kh,
          const f16* __restrict__ Vh, f16* __restrict__ ctx16)
{
    extern __shared__ char smc[];
    const uint32_t smb = smem_u32(smc);
    const int tid = threadIdx.x;
    const int warp = tid >> 5, lane = tid & 31;
    const int q0 = blockIdx.x * 128;
    const int bh = blockIdx.y;

    const f16* qhg = Qh + ((size_t)bh*SEQ + q0)*HDIM;
    const f16* khg = Kh + (size_t)bh*SEQ*HDIM;
    const f16* vhg = Vh + (size_t)bh*SEQ*HDIM;

#pragma unroll
    for (int i = 0; i < 4; ++i) {
        int t = tid + i * 256;
        int r = (t >> 3) & 127;
        int c = t & 7;
        cp16(smb + r * (ASTRIDE*2) + c * 16, qhg + (size_t)r * HDIM + c * 8);
    }
    a_load_kv(smb, 0, 0,   khg, vhg, tid);
    a_load_kv(smb, 1, 64,  khg, vhg, tid);
    a_load_kv(smb, 2, 128, khg, vhg, tid);

    const int gid = lane >> 2, tig = lane & 3;
    const int arow = lane & 15, akh = lane >> 4;
    const int brow = lane & 7, bkh = (lane >> 3) & 1, bpr = lane >> 4;

    uint32_t qf[4][4];
    float o[8][4];
#pragma unroll
    for (int nt = 0; nt < 8; ++nt)
#pragma unroll
        for (int c = 0; c < 4; ++c) o[nt][c] = 0.f;
    float mrow0 = -INFINITY, mrow1 = -INFINITY, lrow0 = 0.f, lrow1 = 0.f;

    int stage = 0;
    for (int kt = 0; kt < SEQ/64; ++kt) {
        uint32_t base = smb + AQTILE_B + stage * AKV_STAGE;
        cp_wait2();
        __syncthreads();

        if (kt == 0) {
#pragma unroll
            for (int kx = 0; kx < 4; ++kx) {
                uint32_t ad = smb + (warp*16 + arow) * (ASTRIDE*2) + (kx*16 + akh*8) * 2;
                ldsm4(qf[kx], ad);
            }
        }

        // S = Q K^T
        float s[8][4];
#pragma unroll
        for (int nt = 0; nt < 8; ++nt)
#pragma unroll
            for (int c = 0; c < 4; ++c) s[nt][c] = 0.f;

#pragma unroll
        for (int kx = 0; kx < 4; ++kx) {
            uint32_t kb[8][2];
#pragma unroll
            for (int p = 0; p < 4; ++p) {
                uint32_t bd = base + (p*16 + bpr*8 + brow) * (ASTRIDE*2)
                            + (kx*16 + bkh*8) * 2;
                uint32_t r[4];
                ldsm4(r, bd);
                kb[2*p][0]=r[0]; kb[2*p][1]=r[1]; kb[2*p+1][0]=r[2]; kb[2*p+1][1]=r[3];
            }
#pragma unroll
            for (int nt = 0; nt < 8; ++nt)
                mma_f16(s[nt], qf[kx], kb[nt]);
        }

        // online softmax (scale 1/8)
        float mx0 = -INFINITY, mx1 = -INFINITY;
#pragma unroll
        for (int nt = 0; nt < 8; ++nt) {
#pragma unroll
            for (int c = 0; c < 4; ++c) s[nt][c] *= 0.125f;
            mx0 = fmaxf(mx0, fmaxf(s[nt][0], s[nt][1]));
            mx1 = fmaxf(mx1, fmaxf(s[nt][2], s[nt][3]));
        }
        mx0 = fmaxf(mx0, __shfl_xor_sync(0xffffffffu, mx0, 1));
        mx0 = fmaxf(mx0, __shfl_xor_sync(0xffffffffu, mx0, 2));
        mx1 = fmaxf(mx1, __shfl_xor_sync(0xffffffffu, mx1, 1));
        mx1 = fmaxf(mx1, __shfl_xor_sync(0xffffffffu, mx1, 2));
        float mn0 = fmaxf(mrow0, mx0), mn1 = fmaxf(mrow1, mx1);
        float al0 = __expf(mrow0 - mn0), al1 = __expf(mrow1 - mn1);
        mrow0 = mn0; mrow1 = mn1;

        float ls0 = 0.f, ls1 = 0.f;
#pragma unroll
        for (int nt = 0; nt < 8; ++nt) {
            s[nt][0] = __expf(s[nt][0] - mn0);
            s[nt][1] = __expf(s[nt][1] - mn0);
            s[nt][2] = __expf(s[nt][2] - mn1);
            s[nt][3] = __expf(s[nt][3] - mn1);
            ls0 += s[nt][0] + s[nt][1];
            ls1 += s[nt][2] + s[nt][3];
        }
        ls0 += __shfl_xor_sync(0xffffffffu, ls0, 1);
        ls0 += __shfl_xor_sync(0xffffffffu, ls0, 2);
        ls1 += __shfl_xor_sync(0xffffffffu, ls1, 1);
        ls1 += __shfl_xor_sync(0xffffffffu, ls1, 2);
        lrow0 = lrow0 * al0 + ls0;
        lrow1 = lrow1 * al1 + ls1;

#pragma unroll
        for (int nt = 0; nt < 8; ++nt) {
            o[nt][0] *= al0; o[nt][1] *= al0;
            o[nt][2] *= al1; o[nt][3] *= al1;
        }

        // pack P into A-fragments
        uint32_t ap[4][4];
#pragma unroll
        for (int j = 0; j < 4; ++j) {
#pragma unroll
            for (int rr = 0; rr < 4; ++rr) {
                int nt = 2*j + (rr >> 1);
                ap[j][rr] = pack_f16(s[nt][(rr & 1)*2], s[nt][(rr & 1)*2 + 1]);
            }
        }

        // O += P V
#pragma unroll
        for (int j = 0; j < 4; ++j) {
            uint32_t vb[8][2];
#pragma unroll
            for (int p = 0; p < 4; ++p) {
                uint32_t vd = base + ATILE_B
                            + (j*16 + (lane & 15)) * (ASTRIDE*2)
                            + (p*16 + (lane >> 4)*8) * 2;
                uint32_t r[4];
                ldsm4t(r, vd);
                vb[2*p][0]=r[0]; vb[2*p][1]=r[1]; vb[2*p+1][0]=r[2]; vb[2*p+1][1]=r[3];
            }
#pragma unroll
            for (int nt = 0; nt < 8; ++nt)
                mma_f16(o[nt], ap[j], vb[nt]);
        }

        __syncthreads();
        if (kt + 3 < SEQ/64) a_load_kv(smb, stage, (kt+3)*64, khg, vhg, tid);
        else                 cp_commit();
        stage = (stage + 1 == ASTAGES) ? 0 : stage + 1;
    }

    // write ctx directly as fp16 (same rounding as the old f32->cvt path)
    const int b = bh >> 4, h = bh & 15;
    float il0 = 1.f / lrow0, il1 = 1.f / lrow1;
    int r0g = q0 + warp*16 + gid;
#pragma unroll
    for (int nt = 0; nt < 8; ++nt) {
        int col = h*HDIM + nt*8 + tig*2;
        *(__half2*)&ctx16[((size_t)(b*SEQ + r0g))*DMODEL + col] =
            __halves2half2(__float2half(o[nt][0]*il0), __float2half(o[nt][1]*il0));
        *(__half2*)&ctx16[((size_t)(b*SEQ + r0g + 8))*DMODEL + col] =
            __halves2half2(__float2half(o[nt][2]*il1), __float2half(o[nt][3]*il1));
    }
}

// ---------------------------------------------------------------------------
// Launch
// ---------------------------------------------------------------------------
extern "C" void kernel_launch(void* const* d_in, const int* in_sizes, int n_in,
                              void* d_out, int out_size)
{
    const float* X  = (const float*)d_in[0];
    const float* Wq = (const float*)d_in[1];
    const float* bq = (const float*)d_in[2];
    const float* Wk = (const float*)d_in[3];
    const float* bk = (const float*)d_in[4];
    const float* Wv = (const float*)d_in[5];
    const float* bv = (const float*)d_in[6];
    const float* Wo = (const float*)d_in[7];
    const float* bo = (const float*)d_in[8];
    float* out = (float*)d_out;

    float *pq, *pk;
    f16 *xh, *wh, *ch, *qh, *kh, *vh;
    cudaGetSymbolAddress((void**)&pq, g_q);
    cudaGetSymbolAddress((void**)&pk, g_k);
    cudaGetSymbolAddress((void**)&xh, g_xh);
    cudaGetSymbolAddress((void**)&wh, g_wh);
    cudaGetSymbolAddress((void**)&ch, g_ch);
    cudaGetSymbolAddress((void**)&qh, g_qh);
    cudaGetSymbolAddress((void**)&kh, g_kh);
    cudaGetSymbolAddress((void**)&vh, g_vh);

    cudaFuncSetAttribute(gemm_hmma<0>, cudaFuncAttributeMaxDynamicSharedMemorySize, GSMEM);
    cudaFuncSetAttribute(gemm_hmma<1>, cudaFuncAttributeMaxDynamicSharedMemorySize, GSMEM);
    cudaFuncSetAttribute(attn_hmma, cudaFuncAttributeMaxDynamicSharedMemorySize, ASMEM);

    // converts: X + all four W in two launches
    cvt_kernel<<<(MTOT*DMODEL/4)/256, 256>>>(X, xh, MTOT*DMODEL/4);
    cvtw_kernel<<<dim3((DMODEL*DMODEL/4)/256, 4), 256>>>(Wq, Wk, Wv, Wo, wh);

    // fused QKV projection (z=0/1 -> f32 q/k; z=2 -> fp16 v directly)
    gemm_hmma<1><<<dim3(DMODEL/128, MTOT/128, 3), 256, GSMEM>>>(
        xh, wh, bq, bk, bv, pq, pk, vh);

    // rope -> fp16 q/k
    rope_cvt<<<(BATCH*NHEAD*SEQ*(HDIM/2))/256, 256>>>(pq, pk, qh, kh);

    // attention (writes fp16 ctx directly)
    attn_hmma<<<dim3(SEQ/128, BATCH*NHEAD), 256, ASMEM>>>(qh, kh, vh, ch);

    // output projection (f32 out)
    gemm_hmma<0><<<dim3(DMODEL/128, MTOT/128, 1), 256, GSMEM>>>(
        ch, wh + 3*1048576, bo, bo, bo, out, out, (f16*)nullptr);
}

// round 10
// speedup vs baseline: 2.5986x; 1.0196x over previous
#include <cuda_runtime.h>
#include <cuda_fp16.h>
#include <math.h>
#include <cstdint>

// Problem constants (fixed by the reference)
#define BATCH 4
#define SEQ   2048
#define DMODEL 1024
#define NHEAD 16
#define HDIM  64
#define MTOT  (BATCH*SEQ)

typedef __half f16;

// ---------------------------------------------------------------------------
// Scratch (device globals)
// ---------------------------------------------------------------------------
__device__ f16 g_xh[MTOT*DMODEL];             // X fp16
__device__ f16 g_wh[4*DMODEL*DMODEL];         // packed Wq,Wk,Wv,Wo fp16
__device__ f16 g_ch[MTOT*DMODEL];             // ctx fp16 (written by attention)

__device__ f16 g_qh[BATCH*NHEAD*SEQ*HDIM];    // post-rope fp16 (GEMM epilogue)
__device__ f16 g_kh[BATCH*NHEAD*SEQ*HDIM];
__device__ f16 g_vh[BATCH*NHEAD*SEQ*HDIM];

__device__ float2 g_rope[SEQ*32];             // (sin, cos) table

// ---------------------------------------------------------------------------
// Helpers
// ---------------------------------------------------------------------------
__device__ __forceinline__ uint32_t smem_u32(const void* p) {
    uint32_t a;
    asm("{ .reg .u64 t; cvta.to.shared.u64 t, %1; cvt.u32.u64 %0, t; }"
        : "=r"(a) : "l"(p));
    return a;
}
__device__ __forceinline__ void cp16(uint32_t dst, const void* src) {
    asm volatile("cp.async.cg.shared.global [%0], [%1], 16;" :: "r"(dst), "l"(src));
}
__device__ __forceinline__ void cp_commit() {
    asm volatile("cp.async.commit_group;" ::: "memory");
}
__device__ __forceinline__ void cp_wait2() {
    asm volatile("cp.async.wait_group 2;" ::: "memory");
}
__device__ __forceinline__ void ldsm4(uint32_t* r, uint32_t addr) {
    asm volatile("ldmatrix.sync.aligned.m8n8.x4.shared.b16 {%0,%1,%2,%3}, [%4];"
                 : "=r"(r[0]), "=r"(r[1]), "=r"(r[2]), "=r"(r[3]) : "r"(addr));
}
__device__ __forceinline__ void ldsm4t(uint32_t* r, uint32_t addr) {
    asm volatile("ldmatrix.sync.aligned.m8n8.x4.trans.shared.b16 {%0,%1,%2,%3}, [%4];"
                 : "=r"(r[0]), "=r"(r[1]), "=r"(r[2]), "=r"(r[3]) : "r"(addr));
}
__device__ __forceinline__ void mma_f16(float* c, const uint32_t* a, const uint32_t* b) {
    asm volatile(
        "mma.sync.aligned.m16n8k16.row.col.f32.f16.f16.f32 "
        "{%0,%1,%2,%3}, {%4,%5,%6,%7}, {%8,%9}, {%0,%1,%2,%3};"
        : "+f"(c[0]), "+f"(c[1]), "+f"(c[2]), "+f"(c[3])
        : "r"(a[0]), "r"(a[1]), "r"(a[2]), "r"(a[3]), "r"(b[0]), "r"(b[1]));
}
__device__ __forceinline__ uint32_t pack_f16(float lo, float hi) {
    uint32_t r;
    asm("cvt.rn.f16x2.f32 %0, %1, %2;" : "=r"(r) : "f"(hi), "f"(lo));
    return r;
}

// ---------------------------------------------------------------------------
// fp32 -> fp16 converts + rope table
// ---------------------------------------------------------------------------
__global__ void cvt_kernel(const float* __restrict__ x, f16* __restrict__ y, int n4)
{
    int i = blockIdx.x * blockDim.x + threadIdx.x;
    if (i >= n4) return;
    float4 v = ((const float4*)x)[i];
    ((__half2*)y)[2*i]   = __halves2half2(__float2half(v.x), __float2half(v.y));
    ((__half2*)y)[2*i+1] = __halves2half2(__float2half(v.z), __float2half(v.w));
}

__global__ void cvtw_kernel(const float* __restrict__ w0, const float* __restrict__ w1,
                            const float* __restrict__ w2, const float* __restrict__ w3,
                            f16* __restrict__ y)
{
    int z = blockIdx.y;
    const float* x = (z == 0) ? w0 : (z == 1) ? w1 : (z == 2) ? w2 : w3;
    f16* dst = y + (size_t)z * DMODEL * DMODEL;
    int i = blockIdx.x * blockDim.x + threadIdx.x;
    float4 v = ((const float4*)x)[i];
    ((__half2*)dst)[2*i]   = __halves2half2(__float2half(v.x), __float2half(v.y));
    ((__half2*)dst)[2*i+1] = __halves2half2(__float2half(v.z), __float2half(v.w));
}

__global__ void rope_table(float2* __restrict__ t)
{
    int idx = blockIdx.x * blockDim.x + threadIdx.x;   // SEQ*32
    int j = idx & 31, s = idx >> 5;
    float inv = powf(10000.f, -(float)j / 32.f);
    float sn, cs;
    sincosf((float)s * inv, &sn, &cs);
    t[idx] = make_float2(sn, cs);
}

// ---------------------------------------------------------------------------
// HMMA GEMM: C[m,n] = sum_k A[m,k]*W[n,k] + bias[n]   (single fp16, f32 acc)
// Tiles: 128x128x32, 8 warps (2M x 4N), warp tile 64x32, 3-stage cp.async.
// MODE 0: f32 row-major out.
// MODE 1: scatter to [B,H,S,HD] fp16; z=0/1 apply RoPE in-epilogue (smem
//         staged, partner column col^32), z=2 write V directly.
// ---------------------------------------------------------------------------
#define GSTRIDE 40                        // fp16 per smem row (32+8 pad)
#define GTILE_B (128*GSTRIDE*2)           // 10240 bytes per tile
#define GSTAGE_B (2*GTILE_B)              // A, W
#define GSTAGES 3
#define GSMEM (GSTAGES*GSTAGE_B)          // 61440 (>= 128*136*2 staging)
#define RSTG 136                          // f16 stride of rope staging tile

__device__ __forceinline__ void g_load_stage(
    uint32_t smb, int s, int kt, int m0, int n0,
    const f16* A, const f16* W, int tid)
{
    uint32_t base = smb + s * GSTAGE_B;
    int kc = kt * 32;
#pragma unroll
    for (int i = 0; i < 4; ++i) {
        int t = tid + i * 256;
        int tile = t >> 9;
        int r = (t >> 2) & 127;
        int c = t & 3;
        const f16* src = (tile == 0) ? A + (size_t)(m0 + r) * DMODEL + kc + c * 8
                                     : W + (size_t)(n0 + r) * DMODEL + kc + c * 8;
        cp16(base + tile * GTILE_B + r * (GSTRIDE*2) + c * 16, src);
    }
    cp_commit();
}

template<int MODE>
__global__ void __launch_bounds__(256, 2)
gemm_hmma(const f16* __restrict__ A, const f16* __restrict__ Wp,
          const float* __restrict__ b0, const float* __restrict__ b1,
          const float* __restrict__ b2,
          float* __restrict__ doutf,
          f16* __restrict__ dq16, f16* __restrict__ dk16, f16* __restrict__ dv16,
          const float2* __restrict__ rope)
{
    extern __shared__ char smc[];
    const uint32_t smb = smem_u32(smc);
    const int tid  = threadIdx.x;
    const int warp = tid >> 5, lane = tid & 31;
    const int z  = blockIdx.z;
    const int m0 = blockIdx.y * 128;
    const int n0 = blockIdx.x * 128;
    const int wm = (warp & 1) * 64;
    const int wn = (warp >> 1) * 32;

    const f16* W = Wp + ((size_t)z << 20);
    const float* bias = (z == 0) ? b0 : (z == 1) ? b1 : b2;

    float acc[4][4][4];
#pragma unroll
    for (int i = 0; i < 4; ++i)
#pragma unroll
        for (int j = 0; j < 4; ++j)
#pragma unroll
            for (int c = 0; c < 4; ++c) acc[i][j][c] = 0.f;

    g_load_stage(smb, 0, 0, m0, n0, A, W, tid);
    g_load_stage(smb, 1, 1, m0, n0, A, W, tid);
    g_load_stage(smb, 2, 2, m0, n0, A, W, tid);

    const int arow = lane & 15, akh = lane >> 4;
    const int brow = lane & 7, bkh = (lane >> 3) & 1, bpr = lane >> 4;

    int stage = 0;
    for (int kt = 0; kt < 32; ++kt) {
        uint32_t base = smb + stage * GSTAGE_B;
        cp_wait2();
        __syncthreads();

#pragma unroll
        for (int kk = 0; kk < 2; ++kk) {
            uint32_t ah[4][4];
#pragma unroll
            for (int mt = 0; mt < 4; ++mt) {
                uint32_t ad = base + (wm + mt*16 + arow) * (GSTRIDE*2)
                                   + (kk*16 + akh*8) * 2;
                ldsm4(ah[mt], ad);
            }
            uint32_t bh[4][2];
#pragma unroll
            for (int p = 0; p < 2; ++p) {
                uint32_t bd = base + GTILE_B
                            + (wn + p*16 + bpr*8 + brow) * (GSTRIDE*2)
                            + (kk*16 + bkh*8) * 2;
                uint32_t r[4];
                ldsm4(r, bd);
                bh[2*p][0]=r[0]; bh[2*p][1]=r[1]; bh[2*p+1][0]=r[2]; bh[2*p+1][1]=r[3];
            }
#pragma unroll
            for (int mt = 0; mt < 4; ++mt)
#pragma unroll
                for (int nt = 0; nt < 4; ++nt)
                    mma_f16(acc[mt][nt], ah[mt], bh[nt]);
        }
        __syncthreads();
        if (kt + 3 < 32) g_load_stage(smb, stage, kt + 3, m0, n0, A, W, tid);
        else             cp_commit();
        stage = (stage + 1 == GSTAGES) ? 0 : stage + 1;
    }

    const int gid = lane >> 2, tig = lane & 3;

    if (MODE == 0) {
#pragma unroll
        for (int mt = 0; mt < 4; ++mt)
#pragma unroll
            for (int nt = 0; nt < 4; ++nt)
#pragma unroll
                for (int half = 0; half < 2; ++half) {
                    int mrow = m0 + wm + mt*16 + gid + half*8;
                    int ncol = n0 + wn + nt*8 + tig*2;
                    float2 v;
                    v.x = acc[mt][nt][half*2]   + bias[ncol];
                    v.y = acc[mt][nt][half*2+1] + bias[ncol+1];
                    *(float2*)&doutf[(size_t)mrow * DMODEL + ncol] = v;
                }
        return;
    }

    if (z == 2) {
        // V: direct fp16 scatter
#pragma unroll
        for (int mt = 0; mt < 4; ++mt)
#pragma unroll
            for (int nt = 0; nt < 4; ++nt)
#pragma unroll
                for (int half = 0; half < 2; ++half) {
                    int mrow = m0 + wm + mt*16 + gid + half*8;
                    int ncol = n0 + wn + nt*8 + tig*2;
                    float vx = acc[mt][nt][half*2]   + bias[ncol];
                    float vy = acc[mt][nt][half*2+1] + bias[ncol+1];
                    int h  = ncol >> 6, hd = ncol & 63;
                    int bb = mrow >> 11, s = mrow & (SEQ-1);
                    size_t off = (((size_t)(bb*NHEAD + h))*SEQ + s)*HDIM + hd;
                    *(__half2*)&dv16[off] =
                        __halves2half2(__float2half(vx), __float2half(vy));
                }
        return;
    }

    // z = 0/1: stage tile (post-bias, f16) in smem, then fused RoPE.
    f16* smf = (f16*)smc;
#pragma unroll
    for (int mt = 0; mt < 4; ++mt)
#pragma unroll
        for (int nt = 0; nt < 4; ++nt)
#pragma unroll
            for (int half = 0; half < 2; ++half) {
                int row  = wm + mt*16 + gid + half*8;
                int colL = wn + nt*8 + tig*2;
                float vx = acc[mt][nt][half*2]   + bias[n0 + colL];
                float vy = acc[mt][nt][half*2+1] + bias[n0 + colL + 1];
                *(__half2*)&smf[row*RSTG + colL] =
                    __halves2half2(__float2half(vx), __float2half(vy));
            }
    __syncthreads();

    f16* dst16 = (z == 0) ? dq16 : dk16;
#pragma unroll
    for (int mt = 0; mt < 4; ++mt)
#pragma unroll
        for (int nt = 0; nt < 4; ++nt)
#pragma unroll
            for (int half = 0; half < 2; ++half) {
                int row  = wm + mt*16 + gid + half*8;
                int colL = wn + nt*8 + tig*2;
                int mrow = m0 + row;
                int ncol = n0 + colL;
                int hd = ncol & 63, h = ncol >> 6;
                int s  = mrow & (SEQ-1), bb = mrow >> 11;
                __half2 own = *(__half2*)&smf[row*RSTG + colL];
                __half2 prt = *(__half2*)&smf[row*RSTG + (colL ^ 32)];
                int j = hd & 31;
                float2 t0 = rope[s*32 + j];
                float2 t1 = rope[s*32 + j + 1];
                float o0x = __half2float(__low2half(own));
                float o1x = __half2float(__high2half(own));
                float p0x = __half2float(__low2half(prt));
                float p1x = __half2float(__high2half(prt));
                float r0, r1;
                if (hd < 32) {        // out = x1*sn - x2*cs
                    r0 = o0x*t0.x - p0x*t0.y;
                    r1 = o1x*t1.x - p1x*t1.y;
                } else {              // out = x2*sn + x1*cs
                    r0 = o0x*t0.x + p0x*t0.y;
                    r1 = o1x*t1.x + p1x*t1.y;
                }
                size_t off = (((size_t)(bb*NHEAD + h))*SEQ + s)*HDIM + hd;
                *(__half2*)&dst16[off] =
                    __halves2half2(__float2half(r0), __float2half(r1));
            }
}

// ---------------------------------------------------------------------------
// Flash attention, single fp16 HMMA. 128-row Q tiles, 8 warps (16 rows each),
// 3-stage cp.async ring of 64-row K/V tiles. 2 CTAs/SM. fp16 ctx output.
// ---------------------------------------------------------------------------
#define ASTRIDE 72
#define ATILE_B (64*ASTRIDE*2)
#define AQTILE_B (128*ASTRIDE*2)
#define AKV_STAGE (2*ATILE_B)
#define ASTAGES 3
#define ASMEM (AQTILE_B + ASTAGES*AKV_STAGE)   // 73728

__device__ __forceinline__ void a_load_kv(
    uint32_t smb, int s, int k0, const f16* kh, const f16* vh, int tid)
{
    uint32_t base = smb + AQTILE_B + s * AKV_STAGE;
#pragma unroll
    for (int i = 0; i < 4; ++i) {
        int t = tid + i * 256;
        int tile = t >> 9;
        int r = (t >> 3) & 63;
        int c = t & 7;
        const f16* src = (tile == 0) ? kh + (size_t)(k0 + r) * HDIM + c * 8
                                     : vh + (size_t)(k0 + r) * HDIM + c * 8;
        cp16(base + tile * ATILE_B + r * (ASTRIDE*2) + c * 16, src);
    }
    cp_commit();
}

__global__ void __launch_bounds__(256, 2)
attn_hmma(const f16* __restrict__ Qh, const f16* __restrict__ Kh,
          const f16* __restrict__ Vh, f16* __restrict__ ctx16)
{
    extern __shared__ char smc[];
    const uint32_t smb = smem_u32(smc);
    const int tid = threadIdx.x;
    const int warp = tid >> 5, lane = tid & 31;
    const int q0 = blockIdx.x * 128;
    const int bh = blockIdx.y;

    const f16* qhg = Qh + ((size_t)bh*SEQ + q0)*HDIM;
    const f16* khg = Kh + (size_t)bh*SEQ*HDIM;
    const f16* vhg = Vh + (size_t)bh*SEQ*HDIM;

#pragma unroll
    for (int i = 0; i < 4; ++i) {
        int t = tid + i * 256;
        int r = (t >> 3) & 127;
        int c = t & 7;
        cp16(smb + r * (ASTRIDE*2) + c * 16, qhg + (size_t)r * HDIM + c * 8);
    }
    a_load_kv(smb, 0, 0,   khg, vhg, tid);
    a_load_kv(smb, 1, 64,  khg, vhg, tid);
    a_load_kv(smb, 2, 128, khg, vhg, tid);

    const int gid = lane >> 2, tig = lane & 3;
    const int arow = lane & 15, akh = lane >> 4;
    const int brow = lane & 7, bkh = (lane >> 3) & 1, bpr = lane >> 4;

    uint32_t qf[4][4];
    float o[8][4];
#pragma unroll
    for (int nt = 0; nt < 8; ++nt)
#pragma unroll
        for (int c = 0; c < 4; ++c) o[nt][c] = 0.f;
    float mrow0 = -INFINITY, mrow1 = -INFINITY, lrow0 = 0.f, lrow1 = 0.f;

    int stage = 0;
    for (int kt = 0; kt < SEQ/64; ++kt) {
        uint32_t base = smb + AQTILE_B + stage * AKV_STAGE;
        cp_wait2();
        __syncthreads();

        if (kt == 0) {
#pragma unroll
            for (int kx = 0; kx < 4; ++kx) {
                uint32_t ad = smb + (warp*16 + arow) * (ASTRIDE*2) + (kx*16 + akh*8) * 2;
                ldsm4(qf[kx], ad);
            }
        }

        float s[8][4];
#pragma unroll
        for (int nt = 0; nt < 8; ++nt)
#pragma unroll
            for (int c = 0; c < 4; ++c) s[nt][c] = 0.f;

#pragma unroll
        for (int kx = 0; kx < 4; ++kx) {
            uint32_t kb[8][2];
#pragma unroll
            for (int p = 0; p < 4; ++p) {
                uint32_t bd = base + (p*16 + bpr*8 + brow) * (ASTRIDE*2)
                            + (kx*16 + bkh*8) * 2;
                uint32_t r[4];
                ldsm4(r, bd);
                kb[2*p][0]=r[0]; kb[2*p][1]=r[1]; kb[2*p+1][0]=r[2]; kb[2*p+1][1]=r[3];
            }
#pragma unroll
            for (int nt = 0; nt < 8; ++nt)
                mma_f16(s[nt], qf[kx], kb[nt]);
        }

        float mx0 = -INFINITY, mx1 = -INFINITY;
#pragma unroll
        for (int nt = 0; nt < 8; ++nt) {
#pragma unroll
            for (int c = 0; c < 4; ++c) s[nt][c] *= 0.125f;
            mx0 = fmaxf(mx0, fmaxf(s[nt][0], s[nt][1]));
            mx1 = fmaxf(mx1, fmaxf(s[nt][2], s[nt][3]));
        }
        mx0 = fmaxf(mx0, __shfl_xor_sync(0xffffffffu, mx0, 1));
        mx0 = fmaxf(mx0, __shfl_xor_sync(0xffffffffu, mx0, 2));
        mx1 = fmaxf(mx1, __shfl_xor_sync(0xffffffffu, mx1, 1));
        mx1 = fmaxf(mx1, __shfl_xor_sync(0xffffffffu, mx1, 2));
        float mn0 = fmaxf(mrow0, mx0), mn1 = fmaxf(mrow1, mx1);
        float al0 = __expf(mrow0 - mn0), al1 = __expf(mrow1 - mn1);
        mrow0 = mn0; mrow1 = mn1;

        float ls0 = 0.f, ls1 = 0.f;
#pragma unroll
        for (int nt = 0; nt < 8; ++nt) {
            s[nt][0] = __expf(s[nt][0] - mn0);
            s[nt][1] = __expf(s[nt][1] - mn0);
            s[nt][2] = __expf(s[nt][2] - mn1);
            s[nt][3] = __expf(s[nt][3] - mn1);
            ls0 += s[nt][0] + s[nt][1];
            ls1 += s[nt][2] + s[nt][3];
        }
        ls0 += __shfl_xor_sync(0xffffffffu, ls0, 1);
        ls0 += __shfl_xor_sync(0xffffffffu, ls0, 2);
        ls1 += __shfl_xor_sync(0xffffffffu, ls1, 1);
        ls1 += __shfl_xor_sync(0xffffffffu, ls1, 2);
        lrow0 = lrow0 * al0 + ls0;
        lrow1 = lrow1 * al1 + ls1;

#pragma unroll
        for (int nt = 0; nt < 8; ++nt) {
            o[nt][0] *= al0; o[nt][1] *= al0;
            o[nt][2] *= al1; o[nt][3] *= al1;
        }

        uint32_t ap[4][4];
#pragma unroll
        for (int j = 0; j < 4; ++j) {
#pragma unroll
            for (int rr = 0; rr < 4; ++rr) {
                int nt = 2*j + (rr >> 1);
                ap[j][rr] = pack_f16(s[nt][(rr & 1)*2], s[nt][(rr & 1)*2 + 1]);
            }
        }

#pragma unroll
        for (int j = 0; j < 4; ++j) {
            uint32_t vb[8][2];
#pragma unroll
            for (int p = 0; p < 4; ++p) {
                uint32_t vd = base + ATILE_B
                            + (j*16 + (lane & 15)) * (ASTRIDE*2)
                            + (p*16 + (lane >> 4)*8) * 2;
                uint32_t r[4];
                ldsm4t(r, vd);
                vb[2*p][0]=r[0]; vb[2*p][1]=r[1]; vb[2*p+1][0]=r[2]; vb[2*p+1][1]=r[3];
            }
#pragma unroll
            for (int nt = 0; nt < 8; ++nt)
                mma_f16(o[nt], ap[j], vb[nt]);
        }

        __syncthreads();
        if (kt + 3 < SEQ/64) a_load_kv(smb, stage, (kt+3)*64, khg, vhg, tid);
        else                 cp_commit();
        stage = (stage + 1 == ASTAGES) ? 0 : stage + 1;
    }

    const int b = bh >> 4, h = bh & 15;
    float il0 = 1.f / lrow0, il1 = 1.f / lrow1;
    int r0g = q0 + warp*16 + gid;
#pragma unroll
    for (int nt = 0; nt < 8; ++nt) {
        int col = h*HDIM + nt*8 + tig*2;
        *(__half2*)&ctx16[((size_t)(b*SEQ + r0g))*DMODEL + col] =
            __halves2half2(__float2half(o[nt][0]*il0), __float2half(o[nt][1]*il0));
        *(__half2*)&ctx16[((size_t)(b*SEQ + r0g + 8))*DMODEL + col] =
            __halves2half2(__float2half(o[nt][2]*il1), __float2half(o[nt][3]*il1));
    }
}

// ---------------------------------------------------------------------------
// Launch
// ---------------------------------------------------------------------------
extern "C" void kernel_launch(void* const* d_in, const int* in_sizes, int n_in,
                              void* d_out, int out_size)
{
    const float* X  = (const float*)d_in[0];
    const float* Wq = (const float*)d_in[1];
    const float* bq = (const float*)d_in[2];
    const float* Wk = (const float*)d_in[3];
    const float* bk = (const float*)d_in[4];
    const float* Wv = (const float*)d_in[5];
    const float* bv = (const float*)d_in[6];
    const float* Wo = (const float*)d_in[7];
    const float* bo = (const float*)d_in[8];
    float* out = (float*)d_out;

    f16 *xh, *wh, *ch, *qh, *kh, *vh;
    float2* rp;
    cudaGetSymbolAddress((void**)&xh, g_xh);
    cudaGetSymbolAddress((void**)&wh, g_wh);
    cudaGetSymbolAddress((void**)&ch, g_ch);
    cudaGetSymbolAddress((void**)&qh, g_qh);
    cudaGetSymbolAddress((void**)&kh, g_kh);
    cudaGetSymbolAddress((void**)&vh, g_vh);
    cudaGetSymbolAddress((void**)&rp, g_rope);

    cudaFuncSetAttribute(gemm_hmma<0>, cudaFuncAttributeMaxDynamicSharedMemorySize, GSMEM);
    cudaFuncSetAttribute(gemm_hmma<1>, cudaFuncAttributeMaxDynamicSharedMemorySize, GSMEM);
    cudaFuncSetAttribute(attn_hmma, cudaFuncAttributeMaxDynamicSharedMemorySize, ASMEM);

    // converts + rope table
    cvt_kernel<<<(MTOT*DMODEL/4)/256, 256>>>(X, xh, MTOT*DMODEL/4);
    cvtw_kernel<<<dim3((DMODEL*DMODEL/4)/256, 4), 256>>>(Wq, Wk, Wv, Wo, wh);
    rope_table<<<(SEQ*32)/256, 256>>>(rp);

    // fused QKV projection + in-epilogue RoPE (z=0/1 -> fp16 q/k; z=2 -> fp16 v)
    gemm_hmma<1><<<dim3(DMODEL/128, MTOT/128, 3), 256, GSMEM>>>(
        xh, wh, bq, bk, bv, nullptr, qh, kh, vh, rp);

    // attention (writes fp16 ctx directly)
    attn_hmma<<<dim3(SEQ/128, BATCH*NHEAD), 256, ASMEM>>>(qh, kh, vh, ch);

    // output projection (f32 out)
    gemm_hmma<0><<<dim3(DMODEL/128, MTOT/128, 1), 256, GSMEM>>>(
        ch, wh + 3*1048576, bo, bo, bo, out, nullptr, nullptr, nullptr, rp);
}